// round 1
// baseline (speedup 1.0000x reference)
#include <cuda_runtime.h>
#include <math.h>

#define HH 160
#define WW 160
#define HWW (160*160)
#define CC 64
#define BB 4

// Intermediate activations (device globals: no allocation allowed)
__device__ float g_off1[BB*CC*HWW];     // conv1 output (also residual input)  26.2 MB
__device__ float g_r  [BB*3*CC*HWW];    // concat(r1,r2,r3)                    78.6 MB
__device__ float g_off[BB*18*HWW];      // offsets                              7.4 MB

// ---------------------------------------------------------------------------
// Kernel 1: 1x1 conv over concat(in_aux, in_ref) (128->64) + LeakyReLU
// one thread = one pixel, acc[64] in regs, weights [ci][co] in smem (LDS.128)
// ---------------------------------------------------------------------------
__global__ __launch_bounds__(256, 2) void k_conv1(
    const float* __restrict__ aux, const float* __restrict__ refi,
    const float* __restrict__ w01, const float* __restrict__ b01)
{
    __shared__ float wsm[128*64];   // [ci][co]
    int tid = threadIdx.x;
    for (int i = tid; i < 128*64; i += 256) {
        int ci = i >> 6, co = i & 63;
        wsm[i] = w01[co*128 + ci];
    }
    __syncthreads();

    int p  = blockIdx.x*256 + tid;
    int b  = p / HWW, hw = p % HWW;
    float acc[64];
    #pragma unroll
    for (int co = 0; co < 64; co++) acc[co] = 0.f;

    const float* ap = aux  + (size_t)b*CC*HWW + hw;
    const float* rp = refi + (size_t)b*CC*HWW + hw;
    for (int ci = 0; ci < 64; ci++) {
        float v = ap[ci*HWW];
        const float* wp = &wsm[ci*64];
        #pragma unroll
        for (int co = 0; co < 64; co++) acc[co] += v * wp[co];
    }
    for (int ci = 0; ci < 64; ci++) {
        float v = rp[ci*HWW];
        const float* wp = &wsm[(64+ci)*64];
        #pragma unroll
        for (int co = 0; co < 64; co++) acc[co] += v * wp[co];
    }

    float* op = g_off1 + (size_t)b*CC*HWW + hw;
    #pragma unroll
    for (int co = 0; co < 64; co++) {
        float v = acc[co] + __ldg(&b01[co]);
        op[co*HWW] = (v >= 0.f) ? v : 0.1f*v;
    }
}

// ---------------------------------------------------------------------------
// Kernel 2: the three dilated 3x3 convs (d = 1,2,4), 64->64, + LeakyReLU,
// writing directly into the concat buffer g_r. One launch, grid.z = B*3.
// 16x16 output tile per CTA, input channels in chunks of 8 staged to smem.
// ---------------------------------------------------------------------------
__global__ __launch_bounds__(256, 2) void k_aspp(
    const float* __restrict__ w1, const float* __restrict__ b1,
    const float* __restrict__ w2, const float* __restrict__ b2,
    const float* __restrict__ w3, const float* __restrict__ b3)
{
    __shared__ float in_s[8*576];      // [ci][24][24] (max halo for d=4)
    __shared__ float w_s [8*9*64];     // [ci][tap][co]

    int z  = blockIdx.z;
    int b  = z & 3, br = z >> 2;       // br: 0,1,2 -> dil 1,2,4
    int DIL = 1 << br;
    const float* aw = (br == 0) ? w1 : (br == 1) ? w2 : w3;
    const float* ab = (br == 0) ? b1 : (br == 1) ? b2 : b3;

    int tid = threadIdx.x;
    int ty = tid >> 4, tx = tid & 15;
    int oy0 = blockIdx.y*16, ox0 = blockIdx.x*16;
    int y0 = oy0 - DIL, x0 = ox0 - DIL;
    int ITD = 16 + 2*DIL;
    int itd2 = ITD*ITD;

    float acc[64];
    #pragma unroll
    for (int co = 0; co < 64; co++) acc[co] = 0.f;

    const float* inb = g_off1 + (size_t)b*CC*HWW;

    for (int c0 = 0; c0 < 64; c0 += 8) {
        // stage input chunk (zero-padded halo)
        int tot = 8*itd2;
        for (int i = tid; i < tot; i += 256) {
            int ci  = i / itd2;
            int rem = i - ci*itd2;
            int yy  = rem / ITD;
            int xx  = rem - yy*ITD;
            int gy = y0 + yy, gx = x0 + xx;
            float v = 0.f;
            if (gy >= 0 && gy < HH && gx >= 0 && gx < WW)
                v = inb[(c0+ci)*HWW + gy*WW + gx];
            in_s[ci*576 + yy*24 + xx] = v;
        }
        // stage weights [ci][tap][co]
        for (int i = tid; i < 8*9*64; i += 256) {
            int co = i & 63;
            int r  = i >> 6;
            int tap = r % 9;
            int ci  = r / 9;
            w_s[(ci*9 + tap)*64 + co] = aw[(co*64 + c0 + ci)*9 + tap];
        }
        __syncthreads();

        for (int ci = 0; ci < 8; ci++) {
            const float* isc = &in_s[ci*576];
            #pragma unroll
            for (int ky = 0; ky < 3; ky++)
            #pragma unroll
            for (int kx = 0; kx < 3; kx++) {
                float v = isc[(ty + ky*DIL)*24 + tx + kx*DIL];
                const float* wp = &w_s[(ci*9 + ky*3 + kx)*64];
                #pragma unroll
                for (int co = 0; co < 64; co++) acc[co] += v * wp[co];
            }
        }
        __syncthreads();
    }

    float* ob = g_r + ((size_t)b*192 + br*64)*HWW + (oy0+ty)*WW + ox0 + tx;
    #pragma unroll
    for (int co = 0; co < 64; co++) {
        float v = acc[co] + __ldg(&ab[co]);
        ob[co*HWW] = (v >= 0.f) ? v : 0.1f*v;
    }
}

// ---------------------------------------------------------------------------
// Kernel 3: fused 1x1 (192->64) + residual + 1x1 offset head (64->18)
// ---------------------------------------------------------------------------
__global__ __launch_bounds__(256, 2) void k_fuse1x1(
    const float* __restrict__ arw, const float* __restrict__ arb,
    const float* __restrict__ w02, const float* __restrict__ b02)
{
    __shared__ float wsm [64*64];   // [ci_chunk][co]
    __shared__ float w2sm[64*18];   // [co][j]
    int tid = threadIdx.x;
    for (int i = tid; i < 64*18; i += 256) {
        int co = i / 18, j = i - co*18;
        w2sm[i] = w02[j*64 + co];
    }

    int p = blockIdx.x*256 + tid;
    int b = p / HWW, hw = p % HWW;

    float t[64];
    #pragma unroll
    for (int co = 0; co < 64; co++) t[co] = 0.f;

    const float* rb = g_r + (size_t)b*192*HWW + hw;
    for (int cc = 0; cc < 192; cc += 64) {
        __syncthreads();
        for (int i = tid; i < 64*64; i += 256) {
            int ci = i >> 6, co = i & 63;
            wsm[i] = arw[co*192 + cc + ci];
        }
        __syncthreads();
        for (int ci = 0; ci < 64; ci++) {
            float v = rb[(cc+ci)*HWW];
            const float* wp = &wsm[ci*64];
            #pragma unroll
            for (int co = 0; co < 64; co++) t[co] += v * wp[co];
        }
    }

    const float* xb = g_off1 + (size_t)b*CC*HWW + hw;
    #pragma unroll
    for (int co = 0; co < 64; co++) t[co] += xb[co*HWW] + __ldg(&arb[co]);

    float* ob = g_off + (size_t)b*18*HWW + hw;
    #pragma unroll
    for (int j = 0; j < 18; j++) {
        float s = __ldg(&b02[j]);
        #pragma unroll
        for (int co = 0; co < 64; co++) s += t[co] * w2sm[co*18 + j];
        ob[j*HWW] = s;
    }
}

// ---------------------------------------------------------------------------
// Kernel 4: deformable 3x3 conv on in_aux with offsets g_off.
// Per pixel: 9 taps x (bilinear gather over 64 ch) x 64 out-ch GEMM.
// dw slice for current tap staged to smem [c][co].
// ---------------------------------------------------------------------------
__global__ __launch_bounds__(256, 2) void k_deform(
    const float* __restrict__ xin, const float* __restrict__ dw,
    const float* __restrict__ db, float* __restrict__ out)
{
    __shared__ float dwsm[64*64];  // [c][co] for current tap
    int tid = threadIdx.x;
    int p  = blockIdx.x*256 + tid;
    int b  = p / HWW, hw = p % HWW;
    int h  = hw / WW, w = hw - h*WW;

    float acc[64];
    #pragma unroll
    for (int co = 0; co < 64; co++) acc[co] = 0.f;

    const float* xb   = xin  + (size_t)b*CC*HWW;
    const float* offb = g_off + (size_t)b*18*HWW + hw;

    for (int k = 0; k < 9; k++) {
        __syncthreads();
        for (int i = tid; i < 64*64; i += 256) {
            int c = i >> 6, co = i & 63;
            dwsm[i] = dw[(co*64 + c)*9 + k];
        }
        __syncthreads();

        int ky = k / 3, kx = k - ky*3;
        float py = (float)(h - 1 + ky) + offb[(2*k  )*HWW];
        float px = (float)(w - 1 + kx) + offb[(2*k+1)*HWW];
        float fy = floorf(py), fx = floorf(px);
        int iy = (int)fy, ix = (int)fx;
        float wy = py - fy, wx = px - fx;

        bool vy0 = (iy   >= 0 && iy   < HH);
        bool vy1 = (iy+1 >= 0 && iy+1 < HH);
        bool vx0 = (ix   >= 0 && ix   < WW);
        bool vx1 = (ix+1 >= 0 && ix+1 < WW);
        float w00 = (1.f-wy)*(1.f-wx); if (!(vy0 && vx0)) w00 = 0.f;
        float w01 = (1.f-wy)*wx;       if (!(vy0 && vx1)) w01 = 0.f;
        float w10 = wy*(1.f-wx);       if (!(vy1 && vx0)) w10 = 0.f;
        float w11 = wy*wx;             if (!(vy1 && vx1)) w11 = 0.f;

        int cy0 = min(max(iy,   0), HH-1), cy1 = min(max(iy+1, 0), HH-1);
        int cx0 = min(max(ix,   0), WW-1), cx1 = min(max(ix+1, 0), WW-1);
        int i00 = cy0*WW + cx0, i01 = cy0*WW + cx1;
        int i10 = cy1*WW + cx0, i11 = cy1*WW + cx1;

        for (int c = 0; c < 64; c++) {
            const float* xp = xb + c*HWW;
            float s = w00*xp[i00] + w01*xp[i01] + w10*xp[i10] + w11*xp[i11];
            const float* wp = &dwsm[c*64];
            #pragma unroll
            for (int co = 0; co < 64; co++) acc[co] += s * wp[co];
        }
    }

    float* ob = out + (size_t)b*CC*HWW + hw;
    #pragma unroll
    for (int co = 0; co < 64; co++) ob[co*HWW] = acc[co] + __ldg(&db[co]);
}

// ---------------------------------------------------------------------------
extern "C" void kernel_launch(void* const* d_in, const int* in_sizes, int n_in,
                              void* d_out, int out_size)
{
    const float* in_aux = (const float*)d_in[0];
    const float* in_ref = (const float*)d_in[1];
    const float* w01    = (const float*)d_in[2];
    const float* b01    = (const float*)d_in[3];
    const float* a1w    = (const float*)d_in[4];
    const float* a1b    = (const float*)d_in[5];
    const float* a2w    = (const float*)d_in[6];
    const float* a2b    = (const float*)d_in[7];
    const float* a3w    = (const float*)d_in[8];
    const float* a3b    = (const float*)d_in[9];
    const float* arw    = (const float*)d_in[10];
    const float* arb    = (const float*)d_in[11];
    const float* w02    = (const float*)d_in[12];
    const float* b02    = (const float*)d_in[13];
    const float* dwp    = (const float*)d_in[14];
    const float* dbp    = (const float*)d_in[15];
    float* out = (float*)d_out;

    k_conv1<<<400, 256>>>(in_aux, in_ref, w01, b01);
    dim3 g2(10, 10, 12);
    k_aspp<<<g2, 256>>>(a1w, a1b, a2w, a2b, a3w, a3b);
    k_fuse1x1<<<400, 256>>>(arw, arb, w02, b02);
    k_deform<<<400, 256>>>(in_aux, dwp, dbp, out);
}

// round 2
// speedup vs baseline: 1.6386x; 1.6386x over previous
#include <cuda_runtime.h>
#include <math.h>

#define HH 160
#define WW 160
#define HWW (160*160)
#define BB 4

typedef unsigned long long u64;

__device__ __forceinline__ u64 ffma2(u64 a, u64 b, u64 c){
    u64 d; asm("fma.rn.f32x2 %0, %1, %2, %3;" : "=l"(d) : "l"(a), "l"(b), "l"(c)); return d;
}
__device__ __forceinline__ u64 pack2(float x){
    u64 d; asm("mov.b64 %0, {%1, %1};" : "=l"(d) : "f"(x), "f"(x)); return d;
}
__device__ __forceinline__ float lo2(u64 a){ return __uint_as_float((unsigned)a); }
__device__ __forceinline__ float hi2(u64 a){ return __uint_as_float((unsigned)(a>>32)); }

// ---------------- device-global scratch (no allocations allowed) -------------
__device__ float g_off1[BB*64*HWW];      // conv1 out / residual      26 MB
__device__ float g_r  [BB*192*HWW];      // concat(r1,r2,r3)          79 MB
__device__ float g_t  [BB*64*HWW];       // fused features            26 MB
__device__ float g_off[BB*18*HWW];       // offsets                    7 MB
__device__ float g_xt [BB*HWW*64];       // in_aux NHWC               26 MB
// transposed weights
__device__ float g_w01t[128*64];         // [ci][co]
__device__ float g_awt [3*64*9*64];      // [br][ci][tap][co]
__device__ float g_arwt[192*64];         // [ci][co]
__device__ float g_w02t[64*18];          // [ci][j]
__device__ float g_dwt [9*64*64];        // [tap][ci][co]

// ---------------------------------------------------------------------------
// prep: transpose all weights into smem-staging-friendly layouts
// ---------------------------------------------------------------------------
__global__ void k_prep(const float* __restrict__ w01, const float* __restrict__ a1w,
                       const float* __restrict__ a2w, const float* __restrict__ a3w,
                       const float* __restrict__ arw, const float* __restrict__ w02,
                       const float* __restrict__ dw)
{
    int i = blockIdx.x*256 + threadIdx.x;
    if (i < 8192) {                       // w01t
        int ci = i>>6, co = i&63;
        g_w01t[i] = w01[co*128 + ci];
        return;
    }
    i -= 8192;
    if (i < 110592) {                     // awt
        int br = i/36864, q = i%36864;
        int ci = q/576, rem = q%576, tap = rem>>6, co = rem&63;
        const float* w = (br==0)?a1w:(br==1)?a2w:a3w;
        g_awt[br*36864 + q] = w[(co*64+ci)*9 + tap];
        return;
    }
    i -= 110592;
    if (i < 12288) {                      // arwt
        int ci = i>>6, co = i&63;
        g_arwt[i] = arw[co*192 + ci];
        return;
    }
    i -= 12288;
    if (i < 1152) {                       // w02t
        int c = i/18, j = i - c*18;
        g_w02t[i] = w02[j*64 + c];
        return;
    }
    i -= 1152;
    if (i < 36864) {                      // dwt
        int k = i/4096, q = i%4096, c = q>>6, co = q&63;
        g_dwt[i] = dw[(co*64+c)*9 + k];
    }
}

// ---------------------------------------------------------------------------
// NCHW -> NHWC transpose of in_aux
// ---------------------------------------------------------------------------
__global__ void k_nhwc(const float* __restrict__ x)
{
    __shared__ float sm[64][33];
    int b = blockIdx.y;
    int hw0 = blockIdx.x*32;
    const float* xp = x + (size_t)b*64*HWW;
    int tid = threadIdx.x;
    int hl = tid&31, cl = tid>>5;
    #pragma unroll
    for (int p = 0; p < 8; p++) {
        int c = cl + p*8;
        sm[c][hl] = xp[(size_t)c*HWW + hw0 + hl];
    }
    __syncthreads();
    int c2 = tid&63, hr = tid>>6;
    float* op = g_xt + ((size_t)b*HWW + hw0)*64;
    #pragma unroll
    for (int p = 0; p < 8; p++) {
        int hh = hr + p*4;
        op[hh*64 + c2] = sm[c2][hh];
    }
}

// ---------------------------------------------------------------------------
// Kernel 1: 1x1 conv concat(aux,ref) 128->64 + LReLU.
// 256 px / CTA, thread = 4 px x 16 co, f32x2 accumulation.
// ---------------------------------------------------------------------------
__global__ __launch_bounds__(256,2) void k_conv1(
    const float* __restrict__ aux, const float* __restrict__ refi,
    const float* __restrict__ b01)
{
    __shared__ float w_s[128*64];
    __shared__ float in_s[8*256];
    int tid = threadIdx.x;
    for (int i = tid; i < 128*64; i += 256) w_s[i] = g_w01t[i];

    int cog = tid>>6, ps = tid&63;
    int pxb = blockIdx.x*256;
    int b = pxb/HWW, hw0 = pxb%HWW;

    u64 acc[4][8];
    #pragma unroll
    for (int j = 0; j < 4; j++)
        #pragma unroll
        for (int t = 0; t < 8; t++) acc[j][t] = 0ull;

    #pragma unroll
    for (int half = 0; half < 2; half++) {
        const float* sp = (half==0 ? aux : refi) + (size_t)b*64*HWW + hw0;
        for (int cc = 0; cc < 64; cc += 8) {
            __syncthreads();
            #pragma unroll
            for (int ci = 0; ci < 8; ci++)
                in_s[ci*256 + tid] = sp[(cc+ci)*HWW + tid];
            __syncthreads();
            const float* wbase = &w_s[(half*64+cc)*64 + cog*16];
            #pragma unroll
            for (int ci = 0; ci < 8; ci++) {
                const ulonglong2* wp = (const ulonglong2*)(wbase + ci*64);
                ulonglong2 wa = wp[0], wb = wp[1], wc = wp[2], wd = wp[3];
                u64 w8[8] = {wa.x,wa.y,wb.x,wb.y,wc.x,wc.y,wd.x,wd.y};
                #pragma unroll
                for (int j = 0; j < 4; j++) {
                    u64 v = pack2(in_s[ci*256 + ps + j*64]);
                    #pragma unroll
                    for (int t = 0; t < 8; t++) acc[j][t] = ffma2(v, w8[t], acc[j][t]);
                }
            }
        }
    }

    float* op = g_off1 + (size_t)b*64*HWW + hw0 + ps;
    #pragma unroll
    for (int j = 0; j < 4; j++)
        #pragma unroll
        for (int t = 0; t < 8; t++) {
            int co0 = cog*16 + 2*t;
            float v0 = lo2(acc[j][t]) + __ldg(&b01[co0]);
            float v1 = hi2(acc[j][t]) + __ldg(&b01[co0+1]);
            op[(size_t)co0*HWW + j*64]     = (v0>=0.f)?v0:0.1f*v0;
            op[(size_t)(co0+1)*HWW + j*64] = (v1>=0.f)?v1:0.1f*v1;
        }
}

// ---------------------------------------------------------------------------
// Kernel 2: dilated 3x3 conv 64->64 + LReLU, one branch per launch (template D)
// 16x16 tile/CTA, ci chunks of 8, thread = 4 px x 16 co.
// ---------------------------------------------------------------------------
template<int D>
__global__ __launch_bounds__(256,2) void k_aspp(int br, const float* __restrict__ bias)
{
    extern __shared__ float dsm[];
    float* in_s = dsm;                  // [8][24*48]
    float* w_s  = dsm + 8*1152;         // [8][9][64]

    const int ITD = 16 + 2*D;
    int b = blockIdx.z;
    int tid = threadIdx.x;
    int cog = tid>>6, ps = tid&63;
    int ty0 = ps>>4, tx = ps&15;
    int oy0 = blockIdx.y*16, ox0 = blockIdx.x*16;
    int y0 = oy0 - D, x0 = ox0 - D;

    u64 acc[4][8];
    #pragma unroll
    for (int j = 0; j < 4; j++)
        #pragma unroll
        for (int t = 0; t < 8; t++) acc[j][t] = 0ull;

    const float* inb = g_off1 + (size_t)b*64*HWW;
    const float* wbr = g_awt + br*36864;

    for (int c0 = 0; c0 < 64; c0 += 8) {
        __syncthreads();
        // stage input 8 x ITD x ITD (row stride 48 for bank-conflict-free reads)
        for (int i = tid; i < 8*ITD*ITD; i += 256) {
            int ci  = i/(ITD*ITD);
            int rem = i - ci*(ITD*ITD);
            int yy  = rem/ITD, xx = rem - yy*ITD;
            int gy = y0 + yy, gx = x0 + xx;
            float v = 0.f;
            if (gy >= 0 && gy < HH && gx >= 0 && gx < WW)
                v = inb[(size_t)(c0+ci)*HWW + gy*WW + gx];
            in_s[ci*1152 + yy*48 + xx] = v;
        }
        // stage weights [ci][tap][co] (coalesced)
        for (int i = tid; i < 8*576; i += 256)
            w_s[i] = wbr[c0*576 + i];
        __syncthreads();

        #pragma unroll
        for (int ci = 0; ci < 8; ci++) {
            const float* isc = &in_s[ci*1152];
            #pragma unroll
            for (int ky = 0; ky < 3; ky++)
                #pragma unroll
                for (int kx = 0; kx < 3; kx++) {
                    const ulonglong2* wp =
                        (const ulonglong2*)&w_s[(ci*9 + ky*3 + kx)*64 + cog*16];
                    ulonglong2 wa = wp[0], wb = wp[1], wc = wp[2], wd = wp[3];
                    u64 w8[8] = {wa.x,wa.y,wb.x,wb.y,wc.x,wc.y,wd.x,wd.y};
                    #pragma unroll
                    for (int j = 0; j < 4; j++) {
                        u64 v = pack2(isc[(ty0 + j*4 + ky*D)*48 + tx + kx*D]);
                        #pragma unroll
                        for (int t = 0; t < 8; t++) acc[j][t] = ffma2(v, w8[t], acc[j][t]);
                    }
                }
        }
    }

    float* ob = g_r + ((size_t)b*192 + br*64)*HWW + (size_t)(oy0+ty0)*WW + ox0 + tx;
    #pragma unroll
    for (int j = 0; j < 4; j++)
        #pragma unroll
        for (int t = 0; t < 8; t++) {
            int co0 = cog*16 + 2*t;
            float v0 = lo2(acc[j][t]) + __ldg(&bias[co0]);
            float v1 = hi2(acc[j][t]) + __ldg(&bias[co0+1]);
            ob[(size_t)co0*HWW + j*4*WW]     = (v0>=0.f)?v0:0.1f*v0;
            ob[(size_t)(co0+1)*HWW + j*4*WW] = (v1>=0.f)?v1:0.1f*v1;
        }
}

// ---------------------------------------------------------------------------
// Kernel 3: 1x1 fuse 192->64 + bias + residual -> g_t
// ---------------------------------------------------------------------------
__global__ __launch_bounds__(256,2) void k_fuse(const float* __restrict__ arb)
{
    extern __shared__ float dsm[];
    float* w_s  = dsm;            // 192*64
    float* in_s = dsm + 192*64;   // 8*256
    int tid = threadIdx.x;
    for (int i = tid; i < 192*64; i += 256) w_s[i] = g_arwt[i];

    int cog = tid>>6, ps = tid&63;
    int pxb = blockIdx.x*256;
    int b = pxb/HWW, hw0 = pxb%HWW;

    u64 acc[4][8];
    #pragma unroll
    for (int j = 0; j < 4; j++)
        #pragma unroll
        for (int t = 0; t < 8; t++) acc[j][t] = 0ull;

    const float* rb = g_r + (size_t)b*192*HWW + hw0;
    for (int cc = 0; cc < 192; cc += 8) {
        __syncthreads();
        #pragma unroll
        for (int ci = 0; ci < 8; ci++)
            in_s[ci*256 + tid] = rb[(size_t)(cc+ci)*HWW + tid];
        __syncthreads();
        #pragma unroll
        for (int ci = 0; ci < 8; ci++) {
            const ulonglong2* wp = (const ulonglong2*)&w_s[(cc+ci)*64 + cog*16];
            ulonglong2 wa = wp[0], wb = wp[1], wc = wp[2], wd = wp[3];
            u64 w8[8] = {wa.x,wa.y,wb.x,wb.y,wc.x,wc.y,wd.x,wd.y};
            #pragma unroll
            for (int j = 0; j < 4; j++) {
                u64 v = pack2(in_s[ci*256 + ps + j*64]);
                #pragma unroll
                for (int t = 0; t < 8; t++) acc[j][t] = ffma2(v, w8[t], acc[j][t]);
            }
        }
    }

    const float* xb = g_off1 + (size_t)b*64*HWW + hw0 + ps;
    float* op = g_t + (size_t)b*64*HWW + hw0 + ps;
    #pragma unroll
    for (int j = 0; j < 4; j++)
        #pragma unroll
        for (int t = 0; t < 8; t++) {
            int co0 = cog*16 + 2*t;
            float v0 = lo2(acc[j][t]) + __ldg(&arb[co0])   + xb[(size_t)co0*HWW + j*64];
            float v1 = hi2(acc[j][t]) + __ldg(&arb[co0+1]) + xb[(size_t)(co0+1)*HWW + j*64];
            op[(size_t)co0*HWW + j*64]     = v0;
            op[(size_t)(co0+1)*HWW + j*64] = v1;
        }
}

// ---------------------------------------------------------------------------
// Kernel 3b: offset head 64->18 (no activation)
// ---------------------------------------------------------------------------
__global__ __launch_bounds__(256,2) void k_head(const float* __restrict__ b02)
{
    __shared__ float w2_s[64*20];
    int tid = threadIdx.x;
    for (int i = tid; i < 64*20; i += 256) {
        int c = i/20, j = i - c*20;
        w2_s[i] = (j < 18) ? g_w02t[c*18 + j] : 0.f;
    }
    __syncthreads();

    int pxb = blockIdx.x*1024;
    int b = pxb/HWW, hw0 = pxb%HWW;

    u64 acc[4][9];
    #pragma unroll
    for (int j = 0; j < 4; j++)
        #pragma unroll
        for (int t = 0; t < 9; t++) acc[j][t] = 0ull;

    const float* tp = g_t + (size_t)b*64*HWW + hw0 + tid;
    for (int c = 0; c < 64; c++) {
        const ulonglong2* wp = (const ulonglong2*)&w2_s[c*20];
        ulonglong2 A = wp[0], B = wp[1], C = wp[2], Dq = wp[3];
        u64 E = *(const u64*)&w2_s[c*20 + 16];
        u64 w9[9] = {A.x,A.y,B.x,B.y,C.x,C.y,Dq.x,Dq.y,E};
        #pragma unroll
        for (int j = 0; j < 4; j++) {
            u64 v = pack2(tp[(size_t)c*HWW + j*256]);
            #pragma unroll
            for (int t = 0; t < 9; t++) acc[j][t] = ffma2(v, w9[t], acc[j][t]);
        }
    }

    float* op = g_off + (size_t)b*18*HWW + hw0 + tid;
    #pragma unroll
    for (int j = 0; j < 4; j++)
        #pragma unroll
        for (int t = 0; t < 9; t++) {
            op[(size_t)(2*t)*HWW + j*256]   = lo2(acc[j][t]) + __ldg(&b02[2*t]);
            op[(size_t)(2*t+1)*HWW + j*256] = hi2(acc[j][t]) + __ldg(&b02[2*t+1]);
        }
}

// ---------------------------------------------------------------------------
// Kernel 4: deformable conv. 128 px / CTA. Per tap:
//  params -> NHWC float4 gathers + bilinear blend into smem -> blocked GEMM.
// ---------------------------------------------------------------------------
__global__ __launch_bounds__(256,2) void k_deform(const float* __restrict__ db,
                                                  float* __restrict__ out)
{
    extern __shared__ float dsm[];
    float* samp_s = dsm;                   // [128][65]
    float* dw_s   = dsm + 128*65;          // [64][64]
    float* pw_s   = dsm + 128*65 + 4096;   // [128][4]
    int*   pi_s   = (int*)(dsm + 128*65 + 4096 + 512); // [128][4]

    int tid = threadIdx.x;
    int pxb = blockIdx.x*128;
    int b = pxb/HWW, hw0 = pxb%HWW;
    int cog = tid>>5, ps = tid&31;

    u64 acc[4][4];
    #pragma unroll
    for (int j = 0; j < 4; j++)
        #pragma unroll
        for (int t = 0; t < 4; t++) acc[j][t] = 0ull;

    const float* xb = g_xt + (size_t)b*HWW*64;

    for (int k = 0; k < 9; k++) {
        __syncthreads();
        // stage this tap's weights [ci][co] (coalesced)
        {
            const float* dwp = g_dwt + k*4096;
            #pragma unroll
            for (int i = 0; i < 16; i++) dw_s[tid + i*256] = dwp[tid + i*256];
        }
        // per-pixel bilinear params
        if (tid < 128) {
            int px = tid, hw = hw0 + px;
            int h = hw/WW, w = hw - h*WW;
            int ky = k/3, kx = k - ky*3;
            const float* offb = g_off + (size_t)b*18*HWW + hw;
            float py  = (float)(h - 1 + ky) + offb[(size_t)(2*k)*HWW];
            float pxf = (float)(w - 1 + kx) + offb[(size_t)(2*k+1)*HWW];
            float fy = floorf(py), fx = floorf(pxf);
            int iy = (int)fy, ix = (int)fx;
            float wy = py - fy, wx = pxf - fx;
            bool vy0 = (iy   >= 0 && iy   < HH);
            bool vy1 = (iy+1 >= 0 && iy+1 < HH);
            bool vx0 = (ix   >= 0 && ix   < WW);
            bool vx1 = (ix+1 >= 0 && ix+1 < WW);
            float w00 = (1.f-wy)*(1.f-wx); if (!(vy0&&vx0)) w00 = 0.f;
            float w01 = (1.f-wy)*wx;       if (!(vy0&&vx1)) w01 = 0.f;
            float w10 = wy*(1.f-wx);       if (!(vy1&&vx0)) w10 = 0.f;
            float w11 = wy*wx;             if (!(vy1&&vx1)) w11 = 0.f;
            int cy0 = min(max(iy,0),HH-1),   cy1 = min(max(iy+1,0),HH-1);
            int cx0 = min(max(ix,0),WW-1),   cx1 = min(max(ix+1,0),WW-1);
            pw_s[px*4+0] = w00; pw_s[px*4+1] = w01;
            pw_s[px*4+2] = w10; pw_s[px*4+3] = w11;
            pi_s[px*4+0] = (cy0*WW + cx0)*64; pi_s[px*4+1] = (cy0*WW + cx1)*64;
            pi_s[px*4+2] = (cy1*WW + cx0)*64; pi_s[px*4+3] = (cy1*WW + cx1)*64;
        }
        __syncthreads();
        // sampling: 2 threads per pixel, 32 channels each
        {
            int px = tid>>1, ch0 = (tid&1)*32;
            float w00 = pw_s[px*4+0], w01v = pw_s[px*4+1];
            float w10 = pw_s[px*4+2], w11  = pw_s[px*4+3];
            int i00 = pi_s[px*4+0], i01 = pi_s[px*4+1];
            int i10 = pi_s[px*4+2], i11 = pi_s[px*4+3];
            float* srow = &samp_s[px*65];
            #pragma unroll
            for (int q = 0; q < 8; q++) {
                int c = ch0 + q*4;
                float4 A = *(const float4*)(xb + i00 + c);
                float4 Bq= *(const float4*)(xb + i01 + c);
                float4 C = *(const float4*)(xb + i10 + c);
                float4 Dq= *(const float4*)(xb + i11 + c);
                srow[c]   = w00*A.x + w01v*Bq.x + w10*C.x + w11*Dq.x;
                srow[c+1] = w00*A.y + w01v*Bq.y + w10*C.y + w11*Dq.y;
                srow[c+2] = w00*A.z + w01v*Bq.z + w10*C.z + w11*Dq.z;
                srow[c+3] = w00*A.w + w01v*Bq.w + w10*C.w + w11*Dq.w;
            }
        }
        __syncthreads();
        // GEMM: 128px x 64co x 64c, thread = 4px x 8co
        for (int c = 0; c < 64; c++) {
            const ulonglong2* wp = (const ulonglong2*)&dw_s[c*64 + cog*8];
            ulonglong2 wa = wp[0], wb = wp[1];
            u64 w4[4] = {wa.x, wa.y, wb.x, wb.y};
            #pragma unroll
            for (int j = 0; j < 4; j++) {
                u64 v = pack2(samp_s[(ps + j*32)*65 + c]);
                #pragma unroll
                for (int t = 0; t < 4; t++) acc[j][t] = ffma2(v, w4[t], acc[j][t]);
            }
        }
    }

    float* op = out + (size_t)b*64*HWW + hw0 + ps;
    #pragma unroll
    for (int j = 0; j < 4; j++)
        #pragma unroll
        for (int t = 0; t < 4; t++) {
            int co0 = cog*8 + 2*t;
            op[(size_t)co0*HWW + j*32]     = lo2(acc[j][t]) + __ldg(&db[co0]);
            op[(size_t)(co0+1)*HWW + j*32] = hi2(acc[j][t]) + __ldg(&db[co0+1]);
        }
}

// ---------------------------------------------------------------------------
extern "C" void kernel_launch(void* const* d_in, const int* in_sizes, int n_in,
                              void* d_out, int out_size)
{
    const float* in_aux = (const float*)d_in[0];
    const float* in_ref = (const float*)d_in[1];
    const float* w01    = (const float*)d_in[2];
    const float* b01    = (const float*)d_in[3];
    const float* a1w    = (const float*)d_in[4];
    const float* a1b    = (const float*)d_in[5];
    const float* a2w    = (const float*)d_in[6];
    const float* a2b    = (const float*)d_in[7];
    const float* a3w    = (const float*)d_in[8];
    const float* a3b    = (const float*)d_in[9];
    const float* arw    = (const float*)d_in[10];
    const float* arb    = (const float*)d_in[11];
    const float* w02    = (const float*)d_in[12];
    const float* b02    = (const float*)d_in[13];
    const float* dwp    = (const float*)d_in[14];
    const float* dbp    = (const float*)d_in[15];
    float* out = (float*)d_out;

    static int inited = 0;
    if (!inited) {
        cudaFuncSetAttribute(k_aspp<1>, cudaFuncAttributeMaxDynamicSharedMemorySize, 55296);
        cudaFuncSetAttribute(k_aspp<2>, cudaFuncAttributeMaxDynamicSharedMemorySize, 55296);
        cudaFuncSetAttribute(k_aspp<4>, cudaFuncAttributeMaxDynamicSharedMemorySize, 55296);
        cudaFuncSetAttribute(k_fuse,    cudaFuncAttributeMaxDynamicSharedMemorySize, 57344);
        cudaFuncSetAttribute(k_deform,  cudaFuncAttributeMaxDynamicSharedMemorySize, 55808);
        inited = 1;
    }

    k_prep<<<661, 256>>>(w01, a1w, a2w, a3w, arw, w02, dwp);
    k_nhwc<<<dim3(800, 4), 256>>>(in_aux);
    k_conv1<<<400, 256>>>(in_aux, in_ref, b01);
    dim3 ga(10, 10, 4);
    k_aspp<1><<<ga, 256, 55296>>>(0, a1b);
    k_aspp<2><<<ga, 256, 55296>>>(1, a2b);
    k_aspp<4><<<ga, 256, 55296>>>(2, a3b);
    k_fuse<<<400, 256, 57344>>>(arb);
    k_head<<<100, 256>>>(b02);
    k_deform<<<800, 256, 55808>>>(dbp, out);
}

// round 5
// speedup vs baseline: 2.0975x; 1.2801x over previous
#include <cuda_runtime.h>
#include <cuda_bf16.h>
#include <math.h>
#include <stdint.h>

#define HH 160
#define WW 160
#define HWW (160*160)
#define BB 4

typedef unsigned long long u64;

// ======================= PTX helpers (base ISA only) ========================
__device__ __forceinline__ u64 ffma2(u64 a, u64 b, u64 c){
    u64 d; asm("fma.rn.f32x2 %0, %1, %2, %3;" : "=l"(d) : "l"(a), "l"(b), "l"(c)); return d;
}
__device__ __forceinline__ u64 pack2(float x){
    u64 d; asm("mov.b64 %0, {%1, %1};" : "=l"(d) : "f"(x), "f"(x)); return d;
}
__device__ __forceinline__ float lo2(u64 a){ return __uint_as_float((unsigned)a); }
__device__ __forceinline__ float hi2(u64 a){ return __uint_as_float((unsigned)(a>>32)); }

__device__ __forceinline__ uint32_t smem_u32(const void* p){
    uint32_t a; asm("{ .reg .u64 t; cvta.to.shared.u64 t, %1; cvt.u32.u64 %0, t; }" : "=r"(a) : "l"(p));
    return a;
}
__device__ __forceinline__ void cp16(uint32_t dst, const void* src){
    asm volatile("cp.async.ca.shared.global [%0], [%1], 16;" :: "r"(dst), "l"(src) : "memory");
}
__device__ __forceinline__ void cp16z(uint32_t dst, const void* src, int sz){
    asm volatile("cp.async.ca.shared.global [%0], [%1], 16, %2;" :: "r"(dst), "l"(src), "r"(sz) : "memory");
}
#define CP_COMMIT() asm volatile("cp.async.commit_group;" ::: "memory")

__device__ __forceinline__ void ldsm4(uint32_t* r, uint32_t a){
    asm volatile("ldmatrix.sync.aligned.m8n8.x4.shared.b16 {%0,%1,%2,%3}, [%4];"
      : "=r"(r[0]),"=r"(r[1]),"=r"(r[2]),"=r"(r[3]) : "r"(a));
}
__device__ __forceinline__ void mma_bf16(float* d, const uint32_t* a, const uint32_t* b){
    asm volatile("mma.sync.aligned.m16n8k16.row.col.f32.bf16.bf16.f32 "
      "{%0,%1,%2,%3}, {%4,%5,%6,%7}, {%8,%9}, {%0,%1,%2,%3};"
      : "+f"(d[0]),"+f"(d[1]),"+f"(d[2]),"+f"(d[3])
      : "r"(a[0]),"r"(a[1]),"r"(a[2]),"r"(a[3]),"r"(b[0]),"r"(b[1]));
}
__device__ __forceinline__ uint32_t swz(uint32_t r){ return r ^ ((r>>3)&0x70); }

// ================= device-global scratch (no allocation allowed) ============
__device__ float g_off1[BB*64*HWW];           // conv1 out NCHW (residual)
__device__ float g_r  [BB*192*HWW];           // concat(r1,r2,r3) NCHW
__device__ float g_t  [BB*64*HWW];            // fused features NCHW
__device__ float g_off[BB*18*HWW];            // offsets NCHW
__device__ float g_xt [BB*HWW*64];            // in_aux NHWC fp32 (deform)
__device__ __nv_bfloat16 g_xh[BB*HWW*64];     // conv1 out NHWC bf16 hi
__device__ __nv_bfloat16 g_xl[BB*HWW*64];     // conv1 out NHWC bf16 lo
__device__ __nv_bfloat16 g_wb[2*3*9*64*64];   // ASPP weights [split][br][tap][co][ci]
// transposed fp32 weights for SIMT kernels
__device__ float g_w01t[128*64];
__device__ float g_arwt[192*64];
__device__ float g_w02t[64*18];
__device__ float g_dwt [9*64*64];

// ---------------------------------------------------------------------------
// prep: weight transposes + bf16 splits
// ---------------------------------------------------------------------------
__global__ void k_prep(const float* __restrict__ w01, const float* __restrict__ a1w,
                       const float* __restrict__ a2w, const float* __restrict__ a3w,
                       const float* __restrict__ arw, const float* __restrict__ w02,
                       const float* __restrict__ dw)
{
    int i = blockIdx.x*256 + threadIdx.x;
    if (i < 8192) { int ci = i>>6, co = i&63; g_w01t[i] = w01[co*128 + ci]; return; }
    i -= 8192;
    if (i < 12288) { int ci = i>>6, co = i&63; g_arwt[i] = arw[co*192 + ci]; return; }
    i -= 12288;
    if (i < 1152) { int c = i/18, j = i - c*18; g_w02t[i] = w02[j*64 + c]; return; }
    i -= 1152;
    if (i < 36864) { int k = i/4096, q = i%4096, c = q>>6, co = q&63;
                     g_dwt[i] = dw[(co*64+c)*9 + k]; return; }
    i -= 36864;
    if (i < 221184) {
        int s  = i / 110592;
        int q  = i % 110592;
        int br = q / 36864;
        int q2 = q % 36864;
        int tap = q2 / 4096;
        int r   = q2 % 4096;
        int co = r >> 6, ci = r & 63;
        const float* w = (br==0)?a1w:(br==1)?a2w:a3w;
        float v = w[(co*64+ci)*9 + tap];
        __nv_bfloat16 h = __float2bfloat16(v);
        if (s == 0) g_wb[i] = h;
        else        g_wb[i] = __float2bfloat16(v - __bfloat162float(h));
    }
}

// ---------------------------------------------------------------------------
// NCHW -> NHWC fp32 transpose of in_aux (for deform sampling)
// ---------------------------------------------------------------------------
__global__ void k_nhwc(const float* __restrict__ x)
{
    __shared__ float sm[64][33];
    int b = blockIdx.y;
    int hw0 = blockIdx.x*32;
    const float* xp = x + (size_t)b*64*HWW;
    int tid = threadIdx.x;
    int hl = tid&31, cl = tid>>5;
    #pragma unroll
    for (int p = 0; p < 8; p++) { int c = cl + p*8; sm[c][hl] = xp[(size_t)c*HWW + hw0 + hl]; }
    __syncthreads();
    int c2 = tid&63, hr = tid>>6;
    float* op = g_xt + ((size_t)b*HWW + hw0)*64;
    #pragma unroll
    for (int p = 0; p < 8; p++) { int hh = hr + p*4; op[hh*64 + c2] = sm[c2][hh]; }
}

// ---------------------------------------------------------------------------
// conv1 output NCHW fp32 -> NHWC bf16 hi/lo (ASPP MMA input)
// ---------------------------------------------------------------------------
__global__ void k_split()
{
    __shared__ float sm[64][33];
    int b = blockIdx.y;
    int hw0 = blockIdx.x*32;
    const float* xp = g_off1 + (size_t)b*64*HWW;
    int tid = threadIdx.x;
    int hl = tid&31, cl = tid>>5;
    #pragma unroll
    for (int p = 0; p < 8; p++) { int c = cl + p*8; sm[c][hl] = xp[(size_t)c*HWW + hw0 + hl]; }
    __syncthreads();
    int c2 = tid&63, hr = tid>>6;
    __nv_bfloat16* oh = g_xh + ((size_t)b*HWW + hw0)*64;
    __nv_bfloat16* ol = g_xl + ((size_t)b*HWW + hw0)*64;
    #pragma unroll
    for (int p = 0; p < 8; p++) {
        int hh = hr + p*4;
        float v = sm[c2][hh];
        __nv_bfloat16 h = __float2bfloat16(v);
        oh[hh*64 + c2] = h;
        ol[hh*64 + c2] = __float2bfloat16(v - __bfloat162float(h));
    }
}

// ---------------------------------------------------------------------------
// Kernel 1: 1x1 conv concat(aux,ref) 128->64 + LReLU (SIMT f32x2)
// ---------------------------------------------------------------------------
__global__ __launch_bounds__(256,2) void k_conv1(
    const float* __restrict__ aux, const float* __restrict__ refi,
    const float* __restrict__ b01)
{
    __shared__ float w_s[128*64];
    __shared__ float in_s[8*256];
    int tid = threadIdx.x;
    for (int i = tid; i < 128*64; i += 256) w_s[i] = g_w01t[i];

    int cog = tid>>6, ps = tid&63;
    int pxb = blockIdx.x*256;
    int b = pxb/HWW, hw0 = pxb%HWW;

    u64 acc[4][8];
    #pragma unroll
    for (int j = 0; j < 4; j++)
        #pragma unroll
        for (int t = 0; t < 8; t++) acc[j][t] = 0ull;

    #pragma unroll
    for (int half = 0; half < 2; half++) {
        const float* sp = (half==0 ? aux : refi) + (size_t)b*64*HWW + hw0;
        for (int cc = 0; cc < 64; cc += 8) {
            __syncthreads();
            #pragma unroll
            for (int ci = 0; ci < 8; ci++)
                in_s[ci*256 + tid] = sp[(cc+ci)*HWW + tid];
            __syncthreads();
            const float* wbase = &w_s[(half*64+cc)*64 + cog*16];
            #pragma unroll
            for (int ci = 0; ci < 8; ci++) {
                const ulonglong2* wp = (const ulonglong2*)(wbase + ci*64);
                ulonglong2 wa = wp[0], wb = wp[1], wc = wp[2], wd = wp[3];
                u64 w8[8] = {wa.x,wa.y,wb.x,wb.y,wc.x,wc.y,wd.x,wd.y};
                #pragma unroll
                for (int j = 0; j < 4; j++) {
                    u64 v = pack2(in_s[ci*256 + ps + j*64]);
                    #pragma unroll
                    for (int t = 0; t < 8; t++) acc[j][t] = ffma2(v, w8[t], acc[j][t]);
                }
            }
        }
    }

    float* op = g_off1 + (size_t)b*64*HWW + hw0 + ps;
    #pragma unroll
    for (int j = 0; j < 4; j++)
        #pragma unroll
        for (int t = 0; t < 8; t++) {
            int co0 = cog*16 + 2*t;
            float v0 = lo2(acc[j][t]) + __ldg(&b01[co0]);
            float v1 = hi2(acc[j][t]) + __ldg(&b01[co0+1]);
            op[(size_t)co0*HWW + j*64]     = (v0>=0.f)?v0:0.1f*v0;
            op[(size_t)(co0+1)*HWW + j*64] = (v1>=0.f)?v1:0.1f*v1;
        }
}

// ---------------------------------------------------------------------------
// Kernel 2: ASPP dilated 3x3 via mma.sync bf16-split tensor cores.
// CTA: 256 thr (8 warps), tile 128px x 64co. Branch weights resident in SMEM
// (144KB, cp.async), A tiles double-buffered cp.async with zfill padding.
// 27 tap-combos (9 taps x {hh, hl, lh}) accumulated in fp32 regs.
// ---------------------------------------------------------------------------
#define ASPP_SMEM 212992

__global__ __launch_bounds__(256,1) void k_aspp_mma(
    const float* __restrict__ b1, const float* __restrict__ b2,
    const float* __restrict__ b3)
{
    extern __shared__ char smem[];
    uint32_t sb = smem_u32(smem);
    int tid = threadIdx.x, lane = tid&31, wid = tid>>5;
    int z = blockIdx.z, b = z&3, br = z>>2;
    int D = 1<<br;
    const float* bias = (br==0)?b1:((br==1)?b2:b3);
    int x0 = blockIdx.x*16, y0 = blockIdx.y*8;

    // ---- stage B: both splits, 9 taps, [co][ci] rows swizzled (144KB) ----
    for (int c = tid; c < 9216; c += 256) {
        int ci8 = c&7, co = (c>>3)&63, ts = c>>9;      // ts: 0..17
        int split = ts/9, tap = ts - split*9;
        const __nv_bfloat16* src =
            g_wb + (((size_t)(split*3+br)*9 + tap)*4096 + co*64 + ci8*8);
        uint32_t rel = (uint32_t)(((split*9+tap)*64 + co)*128 + ci8*16);
        cp16(sb + 65536 + swz(rel), src);
    }

    // ---- A tile issue (stage in {0,1}; splits hi/lo; zfill = padding) ----
    auto issueA = [&](int t, int stage){
        int ky = t/3, kx = t - ky*3;
        int dy = (ky-1)*D, dx = (kx-1)*D;
        #pragma unroll
        for (int j = 0; j < 8; j++) {
            int c = tid + j*256;
            int split = c>>10, rem = c&1023, p = rem>>3, ci8 = rem&7;
            int gy = y0 + (p>>4) + dy, gx = x0 + (p&15) + dx;
            bool ok = (gy>=0)&&(gy<HH)&&(gx>=0)&&(gx<WW);
            const __nv_bfloat16* base = split ? g_xl : g_xh;
            const __nv_bfloat16* src =
                base + (((size_t)b*HWW + (ok ? gy*WW+gx : 0))*64 + ci8*8);
            uint32_t rel = (uint32_t)(p*128 + ci8*16);
            cp16z(sb + (stage*2+split)*16384 + swz(rel), src, ok?16:0);
        }
        CP_COMMIT();
    };
    issueA(0, 0);          // group0 = B + A0
    issueA(1, 1);          // group1 = A1

    int m0 = (wid>>1)*32, n0 = (wid&1)*32;
    float d[2][4][4];
    #pragma unroll
    for (int mt = 0; mt < 2; mt++)
        #pragma unroll
        for (int nt = 0; nt < 4; nt++)
            #pragma unroll
            for (int e = 0; e < 4; e++) d[mt][nt][e] = 0.f;

    #pragma unroll 1
    for (int t = 0; t < 9; t++) {
        if (t < 8) asm volatile("cp.async.wait_group 1;" ::: "memory");
        else       asm volatile("cp.async.wait_group 0;" ::: "memory");
        __syncthreads();
        int stage = t & 1;
        uint32_t Ah = sb + (stage*2+0)*16384;
        uint32_t Al = sb + (stage*2+1)*16384;
        uint32_t Bh = sb + 65536 + (uint32_t)(t*64*128);
        uint32_t Bl = sb + 65536 + (uint32_t)((9+t)*64*128);
        #pragma unroll
        for (int ks = 0; ks < 4; ks++) {
            uint32_t ah[2][4], al[2][4], bh[4][2], bl[4][2];
            #pragma unroll
            for (int mt = 0; mt < 2; mt++) {
                uint32_t rel = (uint32_t)((m0 + mt*16 + (lane&15))*128
                                          + ks*32 + (lane>>4)*16);
                ldsm4(ah[mt], Ah + swz(rel));
                ldsm4(al[mt], Al + swz(rel));
            }
            #pragma unroll
            for (int nt2 = 0; nt2 < 2; nt2++) {
                int mid = lane>>3;
                int row = n0 + nt2*16 + (mid>>1)*8 + (lane&7);
                uint32_t rel = (uint32_t)(row*128 + ks*32 + (mid&1)*16);
                uint32_t r4[4];
                ldsm4(r4, Bh + swz(rel));
                bh[nt2*2][0]=r4[0]; bh[nt2*2][1]=r4[1];
                bh[nt2*2+1][0]=r4[2]; bh[nt2*2+1][1]=r4[3];
                ldsm4(r4, Bl + swz(rel));
                bl[nt2*2][0]=r4[0]; bl[nt2*2][1]=r4[1];
                bl[nt2*2+1][0]=r4[2]; bl[nt2*2+1][1]=r4[3];
            }
            #pragma unroll
            for (int mt = 0; mt < 2; mt++)
                #pragma unroll
                for (int nt = 0; nt < 4; nt++) {
                    mma_bf16(d[mt][nt], ah[mt], bh[nt]);
                    mma_bf16(d[mt][nt], ah[mt], bl[nt]);
                    mma_bf16(d[mt][nt], al[mt], bh[nt]);
                }
        }
        __syncthreads();
        if (t < 7) issueA(t+2, stage);
    }

    // ---- epilogue: transpose through smem (reuse A region), coalesced out --
    float* ep = (float*)smem;              // [64co][128px]
    #pragma unroll
    for (int mt = 0; mt < 2; mt++)
        #pragma unroll
        for (int nt = 0; nt < 4; nt++) {
            int px = m0 + mt*16 + (lane>>2);
            int co = n0 + nt*8 + (lane&3)*2;
            ep[co*128 + px]       = d[mt][nt][0];
            ep[(co+1)*128 + px]   = d[mt][nt][1];
            ep[co*128 + px+8]     = d[mt][nt][2];
            ep[(co+1)*128 + px+8] = d[mt][nt][3];
        }
    __syncthreads();
    float* ob = g_r + ((size_t)b*192 + br*64)*HWW;
    for (int i = tid; i < 8192; i += 256) {
        int co = i>>7, p = i&127, y = p>>4, x = p&15;
        float v = ep[i] + __ldg(&bias[co]);
        v = (v >= 0.f) ? v : 0.1f*v;
        ob[(size_t)co*HWW + (size_t)(y0+y)*WW + x0 + x] = v;
    }
}

// ---------------------------------------------------------------------------
// Kernel 3: 1x1 fuse 192->64 + bias + residual -> g_t (SIMT f32x2)
// ---------------------------------------------------------------------------
__global__ __launch_bounds__(256,2) void k_fuse(const float* __restrict__ arb)
{
    extern __shared__ float dsm[];
    float* w_s  = dsm;            // 192*64
    float* in_s = dsm + 192*64;   // 8*256
    int tid = threadIdx.x;
    for (int i = tid; i < 192*64; i += 256) w_s[i] = g_arwt[i];

    int cog = tid>>6, ps = tid&63;
    int pxb = blockIdx.x*256;
    int b = pxb/HWW, hw0 = pxb%HWW;

    u64 acc[4][8];
    #pragma unroll
    for (int j = 0; j < 4; j++)
        #pragma unroll
        for (int t = 0; t < 8; t++) acc[j][t] = 0ull;

    const float* rb = g_r + (size_t)b*192*HWW + hw0;
    for (int cc = 0; cc < 192; cc += 8) {
        __syncthreads();
        #pragma unroll
        for (int ci = 0; ci < 8; ci++)
            in_s[ci*256 + tid] = rb[(size_t)(cc+ci)*HWW + tid];
        __syncthreads();
        #pragma unroll
        for (int ci = 0; ci < 8; ci++) {
            const ulonglong2* wp = (const ulonglong2*)&w_s[(cc+ci)*64 + cog*16];
            ulonglong2 wa = wp[0], wb = wp[1], wc = wp[2], wd = wp[3];
            u64 w8[8] = {wa.x,wa.y,wb.x,wb.y,wc.x,wc.y,wd.x,wd.y};
            #pragma unroll
            for (int j = 0; j < 4; j++) {
                u64 v = pack2(in_s[ci*256 + ps + j*64]);
                #pragma unroll
                for (int t = 0; t < 8; t++) acc[j][t] = ffma2(v, w8[t], acc[j][t]);
            }
        }
    }

    const float* xb = g_off1 + (size_t)b*64*HWW + hw0 + ps;
    float* op = g_t + (size_t)b*64*HWW + hw0 + ps;
    #pragma unroll
    for (int j = 0; j < 4; j++)
        #pragma unroll
        for (int t = 0; t < 8; t++) {
            int co0 = cog*16 + 2*t;
            float v0 = lo2(acc[j][t]) + __ldg(&arb[co0])   + xb[(size_t)co0*HWW + j*64];
            float v1 = hi2(acc[j][t]) + __ldg(&arb[co0+1]) + xb[(size_t)(co0+1)*HWW + j*64];
            op[(size_t)co0*HWW + j*64]     = v0;
            op[(size_t)(co0+1)*HWW + j*64] = v1;
        }
}

// ---------------------------------------------------------------------------
// Kernel 3b: offset head 64->18
// ---------------------------------------------------------------------------
__global__ __launch_bounds__(256,2) void k_head(const float* __restrict__ b02)
{
    __shared__ float w2_s[64*20];
    int tid = threadIdx.x;
    for (int i = tid; i < 64*20; i += 256) {
        int c = i/20, j = i - c*20;
        w2_s[i] = (j < 18) ? g_w02t[c*18 + j] : 0.f;
    }
    __syncthreads();

    int pxb = blockIdx.x*1024;
    int b = pxb/HWW, hw0 = pxb%HWW;

    u64 acc[4][9];
    #pragma unroll
    for (int j = 0; j < 4; j++)
        #pragma unroll
        for (int t = 0; t < 9; t++) acc[j][t] = 0ull;

    const float* tp = g_t + (size_t)b*64*HWW + hw0 + tid;
    for (int c = 0; c < 64; c++) {
        const ulonglong2* wp = (const ulonglong2*)&w2_s[c*20];
        ulonglong2 A = wp[0], B = wp[1], C = wp[2], Dq = wp[3];
        u64 E = *(const u64*)&w2_s[c*20 + 16];
        u64 w9[9] = {A.x,A.y,B.x,B.y,C.x,C.y,Dq.x,Dq.y,E};
        #pragma unroll
        for (int j = 0; j < 4; j++) {
            u64 v = pack2(tp[(size_t)c*HWW + j*256]);
            #pragma unroll
            for (int t = 0; t < 9; t++) acc[j][t] = ffma2(v, w9[t], acc[j][t]);
        }
    }

    float* op = g_off + (size_t)b*18*HWW + hw0 + tid;
    #pragma unroll
    for (int j = 0; j < 4; j++)
        #pragma unroll
        for (int t = 0; t < 9; t++) {
            op[(size_t)(2*t)*HWW + j*256]   = lo2(acc[j][t]) + __ldg(&b02[2*t]);
            op[(size_t)(2*t+1)*HWW + j*256] = hi2(acc[j][t]) + __ldg(&b02[2*t+1]);
        }
}

// ---------------------------------------------------------------------------
// Kernel 4: deformable conv (SIMT; NHWC float4 gathers + blocked GEMM)
// ---------------------------------------------------------------------------
__global__ __launch_bounds__(256,2) void k_deform(const float* __restrict__ db,
                                                  float* __restrict__ out)
{
    extern __shared__ float dsm[];
    float* samp_s = dsm;                   // [128][65]
    float* dw_s   = dsm + 128*65;          // [64][64]
    float* pw_s   = dsm + 128*65 + 4096;   // [128][4]
    int*   pi_s   = (int*)(dsm + 128*65 + 4096 + 512); // [128][4]

    int tid = threadIdx.x;
    int pxb = blockIdx.x*128;
    int b = pxb/HWW, hw0 = pxb%HWW;
    int cog = tid>>5, ps = tid&31;

    u64 acc[4][4];
    #pragma unroll
    for (int j = 0; j < 4; j++)
        #pragma unroll
        for (int t = 0; t < 4; t++) acc[j][t] = 0ull;

    const float* xb = g_xt + (size_t)b*HWW*64;

    for (int k = 0; k < 9; k++) {
        __syncthreads();
        {
            const float* dwp = g_dwt + k*4096;
            #pragma unroll
            for (int i = 0; i < 16; i++) dw_s[tid + i*256] = dwp[tid + i*256];
        }
        if (tid < 128) {
            int px = tid, hw = hw0 + px;
            int h = hw/WW, w = hw - h*WW;
            int ky = k/3, kx = k - ky*3;
            const float* offb = g_off + (size_t)b*18*HWW + hw;
            float py  = (float)(h - 1 + ky) + offb[(size_t)(2*k)*HWW];
            float pxf = (float)(w - 1 + kx) + offb[(size_t)(2*k+1)*HWW];
            float fy = floorf(py), fx = floorf(pxf);
            int iy = (int)fy, ix = (int)fx;
            float wy = py - fy, wx = pxf - fx;
            bool vy0 = (iy   >= 0 && iy   < HH);
            bool vy1 = (iy+1 >= 0 && iy+1 < HH);
            bool vx0 = (ix   >= 0 && ix   < WW);
            bool vx1 = (ix+1 >= 0 && ix+1 < WW);
            float w00 = (1.f-wy)*(1.f-wx); if (!(vy0&&vx0)) w00 = 0.f;
            float w01 = (1.f-wy)*wx;       if (!(vy0&&vx1)) w01 = 0.f;
            float w10 = wy*(1.f-wx);       if (!(vy1&&vx0)) w10 = 0.f;
            float w11 = wy*wx;             if (!(vy1&&vx1)) w11 = 0.f;
            int cy0 = min(max(iy,0),HH-1),   cy1 = min(max(iy+1,0),HH-1);
            int cx0 = min(max(ix,0),WW-1),   cx1 = min(max(ix+1,0),WW-1);
            pw_s[px*4+0] = w00; pw_s[px*4+1] = w01;
            pw_s[px*4+2] = w10; pw_s[px*4+3] = w11;
            pi_s[px*4+0] = (cy0*WW + cx0)*64; pi_s[px*4+1] = (cy0*WW + cx1)*64;
            pi_s[px*4+2] = (cy1*WW + cx0)*64; pi_s[px*4+3] = (cy1*WW + cx1)*64;
        }
        __syncthreads();
        {
            int px = tid>>1, ch0 = (tid&1)*32;
            float w00 = pw_s[px*4+0], w01v = pw_s[px*4+1];
            float w10 = pw_s[px*4+2], w11  = pw_s[px*4+3];
            int i00 = pi_s[px*4+0], i01 = pi_s[px*4+1];
            int i10 = pi_s[px*4+2], i11 = pi_s[px*4+3];
            float* srow = &samp_s[px*65];
            #pragma unroll
            for (int q = 0; q < 8; q++) {
                int c = ch0 + q*4;
                float4 A = *(const float4*)(xb + i00 + c);
                float4 Bq= *(const float4*)(xb + i01 + c);
                float4 C = *(const float4*)(xb + i10 + c);
                float4 Dq= *(const float4*)(xb + i11 + c);
                srow[c]   = w00*A.x + w01v*Bq.x + w10*C.x + w11*Dq.x;
                srow[c+1] = w00*A.y + w01v*Bq.y + w10*C.y + w11*Dq.y;
                srow[c+2] = w00*A.z + w01v*Bq.z + w10*C.z + w11*Dq.z;
                srow[c+3] = w00*A.w + w01v*Bq.w + w10*C.w + w11*Dq.w;
            }
        }
        __syncthreads();
        for (int c = 0; c < 64; c++) {
            const ulonglong2* wp = (const ulonglong2*)&dw_s[c*64 + cog*8];
            ulonglong2 wa = wp[0], wb = wp[1];
            u64 w4[4] = {wa.x, wa.y, wb.x, wb.y};
            #pragma unroll
            for (int j = 0; j < 4; j++) {
                u64 v = pack2(samp_s[(ps + j*32)*65 + c]);
                #pragma unroll
                for (int t = 0; t < 4; t++) acc[j][t] = ffma2(v, w4[t], acc[j][t]);
            }
        }
    }

    float* op = out + (size_t)b*64*HWW + hw0 + ps;
    #pragma unroll
    for (int j = 0; j < 4; j++)
        #pragma unroll
        for (int t = 0; t < 4; t++) {
            int co0 = cog*8 + 2*t;
            op[(size_t)co0*HWW + j*32]     = lo2(acc[j][t]) + __ldg(&db[co0]);
            op[(size_t)(co0+1)*HWW + j*32] = hi2(acc[j][t]) + __ldg(&db[co0+1]);
        }
}

// ===========================================================================
extern "C" void kernel_launch(void* const* d_in, const int* in_sizes, int n_in,
                              void* d_out, int out_size)
{
    const float* in_aux = (const float*)d_in[0];
    const float* in_ref = (const float*)d_in[1];
    const float* w01    = (const float*)d_in[2];
    const float* b01    = (const float*)d_in[3];
    const float* a1w    = (const float*)d_in[4];
    const float* a1b    = (const float*)d_in[5];
    const float* a2w    = (const float*)d_in[6];
    const float* a2b    = (const float*)d_in[7];
    const float* a3w    = (const float*)d_in[8];
    const float* a3b    = (const float*)d_in[9];
    const float* arw    = (const float*)d_in[10];
    const float* arb    = (const float*)d_in[11];
    const float* w02    = (const float*)d_in[12];
    const float* b02    = (const float*)d_in[13];
    const float* dwp    = (const float*)d_in[14];
    const float* dbp    = (const float*)d_in[15];
    float* out = (float*)d_out;

    static int s_inited = 0;
    if (!s_inited) {
        cudaFuncSetAttribute(k_aspp_mma, cudaFuncAttributeMaxDynamicSharedMemorySize, ASPP_SMEM);
        cudaFuncSetAttribute(k_fuse,     cudaFuncAttributeMaxDynamicSharedMemorySize, 57344);
        cudaFuncSetAttribute(k_deform,   cudaFuncAttributeMaxDynamicSharedMemorySize, 55808);
        s_inited = 1;
    }

    k_prep<<<1093, 256>>>(w01, a1w, a2w, a3w, arw, w02, dwp);
    k_nhwc<<<dim3(800, 4), 256>>>(in_aux);
    k_conv1<<<400, 256>>>(in_aux, in_ref, b01);
    k_split<<<dim3(800, 4), 256>>>();

    dim3 ga(10, 20, 12);
    k_aspp_mma<<<ga, 256, ASPP_SMEM>>>(a1b, a2b, a3b);

    k_fuse<<<400, 256, 57344>>>(arb);
    k_head<<<100, 256>>>(b02);
    k_deform<<<800, 256, 55808>>>(dbp, out);
}

// round 6
// speedup vs baseline: 2.2075x; 1.0524x over previous
#include <cuda_runtime.h>
#include <cuda_bf16.h>
#include <math.h>
#include <stdint.h>

#define HH 160
#define WW 160
#define HWW (160*160)
#define BB 4

typedef unsigned long long u64;

// ======================= PTX helpers (base ISA only) ========================
__device__ __forceinline__ u64 ffma2(u64 a, u64 b, u64 c){
    u64 d; asm("fma.rn.f32x2 %0, %1, %2, %3;" : "=l"(d) : "l"(a), "l"(b), "l"(c)); return d;
}
__device__ __forceinline__ u64 pack2(float x){
    u64 d; asm("mov.b64 %0, {%1, %1};" : "=l"(d) : "f"(x), "f"(x)); return d;
}
__device__ __forceinline__ float lo2(u64 a){ return __uint_as_float((unsigned)a); }
__device__ __forceinline__ float hi2(u64 a){ return __uint_as_float((unsigned)(a>>32)); }

__device__ __forceinline__ uint32_t smem_u32(const void* p){
    uint32_t a; asm("{ .reg .u64 t; cvta.to.shared.u64 t, %1; cvt.u32.u64 %0, t; }" : "=r"(a) : "l"(p));
    return a;
}
__device__ __forceinline__ void cp16(uint32_t dst, const void* src){
    asm volatile("cp.async.ca.shared.global [%0], [%1], 16;" :: "r"(dst), "l"(src) : "memory");
}
__device__ __forceinline__ void cp16z(uint32_t dst, const void* src, int sz){
    asm volatile("cp.async.ca.shared.global [%0], [%1], 16, %2;" :: "r"(dst), "l"(src), "r"(sz) : "memory");
}
#define CP_COMMIT() asm volatile("cp.async.commit_group;" ::: "memory")

__device__ __forceinline__ void ldsm4(uint32_t* r, uint32_t a){
    asm volatile("ldmatrix.sync.aligned.m8n8.x4.shared.b16 {%0,%1,%2,%3}, [%4];"
      : "=r"(r[0]),"=r"(r[1]),"=r"(r[2]),"=r"(r[3]) : "r"(a));
}
__device__ __forceinline__ void mma_bf16(float* d, const uint32_t* a, const uint32_t* b){
    asm volatile("mma.sync.aligned.m16n8k16.row.col.f32.bf16.bf16.f32 "
      "{%0,%1,%2,%3}, {%4,%5,%6,%7}, {%8,%9}, {%0,%1,%2,%3};"
      : "+f"(d[0]),"+f"(d[1]),"+f"(d[2]),"+f"(d[3])
      : "r"(a[0]),"r"(a[1]),"r"(a[2]),"r"(a[3]),"r"(b[0]),"r"(b[1]));
}
__device__ __forceinline__ uint32_t swz(uint32_t r){ return r ^ ((r>>3)&0x70); }

// ================= device-global scratch (no allocation allowed) ============
__device__ __align__(16) float g_off1[BB*64*HWW];        // conv1 out NCHW (residual)
__device__ __align__(16) float g_t  [BB*64*HWW];         // fused features NCHW
__device__ __align__(16) float g_off[BB*18*HWW];         // offsets NCHW
__device__ __align__(16) float g_xt [BB*HWW*64];         // in_aux NHWC fp32 (deform)
__device__ __align__(16) __nv_bfloat16 g_xh[BB*HWW*64];  // conv1 out NHWC bf16 hi
__device__ __align__(16) __nv_bfloat16 g_xl[BB*HWW*64];  // conv1 out NHWC bf16 lo
__device__ __align__(16) __nv_bfloat16 g_rh[(size_t)BB*HWW*192]; // concat NHWC hi
__device__ __align__(16) __nv_bfloat16 g_rl[(size_t)BB*HWW*192]; // concat NHWC lo
__device__ __align__(16) __nv_bfloat16 g_wb  [2*3*9*64*64]; // ASPP W [split][br][tap][co][ci]
__device__ __align__(16) __nv_bfloat16 g_arwb[2*3*64*64];   // fuse W [split][sub][co][ci]
__device__ __align__(16) __nv_bfloat16 g_dwb [2*9*64*64];   // deform W [split][tap][co][ci]
__device__ float g_w01t[128*64];
__device__ float g_w02t[64*18];

// ---------------------------------------------------------------------------
// prep: weight transposes + bf16 splits
// ---------------------------------------------------------------------------
__global__ void k_prep(const float* __restrict__ w01, const float* __restrict__ a1w,
                       const float* __restrict__ a2w, const float* __restrict__ a3w,
                       const float* __restrict__ arw, const float* __restrict__ w02,
                       const float* __restrict__ dw)
{
    int i = blockIdx.x*256 + threadIdx.x;
    if (i < 8192) { int ci = i>>6, co = i&63; g_w01t[i] = w01[co*128 + ci]; return; }
    i -= 8192;
    if (i < 1152) { int c = i/18, j = i - c*18; g_w02t[i] = w02[j*64 + c]; return; }
    i -= 1152;
    if (i < 221184) {
        int s  = i / 110592;
        int q  = i % 110592;
        int br = q / 36864;
        int q2 = q % 36864;
        int tap = q2 / 4096;
        int r   = q2 % 4096;
        int co = r >> 6, ci = r & 63;
        const float* w = (br==0)?a1w:(br==1)?a2w:a3w;
        float v = w[(co*64+ci)*9 + tap];
        __nv_bfloat16 h = __float2bfloat16(v);
        g_wb[i] = (s==0) ? h : __float2bfloat16(v - __bfloat162float(h));
        return;
    }
    i -= 221184;
    if (i < 24576) {
        int s = i / 12288, q = i % 12288;
        int sub = q / 4096, r = q % 4096;
        int co = r >> 6, ci = r & 63;
        float v = arw[co*192 + sub*64 + ci];
        __nv_bfloat16 h = __float2bfloat16(v);
        g_arwb[i] = (s==0) ? h : __float2bfloat16(v - __bfloat162float(h));
        return;
    }
    i -= 24576;
    if (i < 73728) {
        int s = i / 36864, q = i % 36864;
        int tap = q / 4096, r = q % 4096;
        int co = r >> 6, ci = r & 63;
        float v = dw[(co*64+ci)*9 + tap];
        __nv_bfloat16 h = __float2bfloat16(v);
        g_dwb[i] = (s==0) ? h : __float2bfloat16(v - __bfloat162float(h));
    }
}

// ---------------------------------------------------------------------------
// NCHW -> NHWC fp32 transpose of in_aux (for deform sampling)
// ---------------------------------------------------------------------------
__global__ void k_nhwc(const float* __restrict__ x)
{
    __shared__ float sm[64][33];
    int b = blockIdx.y;
    int hw0 = blockIdx.x*32;
    const float* xp = x + (size_t)b*64*HWW;
    int tid = threadIdx.x;
    int hl = tid&31, cl = tid>>5;
    #pragma unroll
    for (int p = 0; p < 8; p++) { int c = cl + p*8; sm[c][hl] = xp[(size_t)c*HWW + hw0 + hl]; }
    __syncthreads();
    int c2 = tid&63, hr = tid>>6;
    float* op = g_xt + ((size_t)b*HWW + hw0)*64;
    #pragma unroll
    for (int p = 0; p < 8; p++) { int hh = hr + p*4; op[hh*64 + c2] = sm[c2][hh]; }
}

// ---------------------------------------------------------------------------
// conv1 output NCHW fp32 -> NHWC bf16 hi/lo (ASPP MMA input)
// ---------------------------------------------------------------------------
__global__ void k_split()
{
    __shared__ float sm[64][33];
    int b = blockIdx.y;
    int hw0 = blockIdx.x*32;
    const float* xp = g_off1 + (size_t)b*64*HWW;
    int tid = threadIdx.x;
    int hl = tid&31, cl = tid>>5;
    #pragma unroll
    for (int p = 0; p < 8; p++) { int c = cl + p*8; sm[c][hl] = xp[(size_t)c*HWW + hw0 + hl]; }
    __syncthreads();
    int c2 = tid&63, hr = tid>>6;
    __nv_bfloat16* oh = g_xh + ((size_t)b*HWW + hw0)*64;
    __nv_bfloat16* ol = g_xl + ((size_t)b*HWW + hw0)*64;
    #pragma unroll
    for (int p = 0; p < 8; p++) {
        int hh = hr + p*4;
        float v = sm[c2][hh];
        __nv_bfloat16 h = __float2bfloat16(v);
        oh[hh*64 + c2] = h;
        ol[hh*64 + c2] = __float2bfloat16(v - __bfloat162float(h));
    }
}

// ---------------------------------------------------------------------------
// Kernel 1: 1x1 conv concat(aux,ref) 128->64 + LReLU (SIMT f32x2)
// ---------------------------------------------------------------------------
__global__ __launch_bounds__(256,2) void k_conv1(
    const float* __restrict__ aux, const float* __restrict__ refi,
    const float* __restrict__ b01)
{
    __shared__ float w_s[128*64];
    __shared__ float in_s[8*256];
    int tid = threadIdx.x;
    for (int i = tid; i < 128*64; i += 256) w_s[i] = g_w01t[i];

    int cog = tid>>6, ps = tid&63;
    int pxb = blockIdx.x*256;
    int b = pxb/HWW, hw0 = pxb%HWW;

    u64 acc[4][8];
    #pragma unroll
    for (int j = 0; j < 4; j++)
        #pragma unroll
        for (int t = 0; t < 8; t++) acc[j][t] = 0ull;

    #pragma unroll
    for (int half = 0; half < 2; half++) {
        const float* sp = (half==0 ? aux : refi) + (size_t)b*64*HWW + hw0;
        for (int cc = 0; cc < 64; cc += 8) {
            __syncthreads();
            #pragma unroll
            for (int ci = 0; ci < 8; ci++)
                in_s[ci*256 + tid] = sp[(cc+ci)*HWW + tid];
            __syncthreads();
            const float* wbase = &w_s[(half*64+cc)*64 + cog*16];
            #pragma unroll
            for (int ci = 0; ci < 8; ci++) {
                const ulonglong2* wp = (const ulonglong2*)(wbase + ci*64);
                ulonglong2 wa = wp[0], wb = wp[1], wc = wp[2], wd = wp[3];
                u64 w8[8] = {wa.x,wa.y,wb.x,wb.y,wc.x,wc.y,wd.x,wd.y};
                #pragma unroll
                for (int j = 0; j < 4; j++) {
                    u64 v = pack2(in_s[ci*256 + ps + j*64]);
                    #pragma unroll
                    for (int t = 0; t < 8; t++) acc[j][t] = ffma2(v, w8[t], acc[j][t]);
                }
            }
        }
    }

    float* op = g_off1 + (size_t)b*64*HWW + hw0 + ps;
    #pragma unroll
    for (int j = 0; j < 4; j++)
        #pragma unroll
        for (int t = 0; t < 8; t++) {
            int co0 = cog*16 + 2*t;
            float v0 = lo2(acc[j][t]) + __ldg(&b01[co0]);
            float v1 = hi2(acc[j][t]) + __ldg(&b01[co0+1]);
            op[(size_t)co0*HWW + j*64]     = (v0>=0.f)?v0:0.1f*v0;
            op[(size_t)(co0+1)*HWW + j*64] = (v1>=0.f)?v1:0.1f*v1;
        }
}

// ---------------------------------------------------------------------------
// Kernel 2: ASPP dilated 3x3 via mma.sync bf16-split; epilogue writes bf16
// hi/lo NHWC concat buffer (g_rh/g_rl) directly.
// ---------------------------------------------------------------------------
#define ASPP_SMEM 212992

__global__ __launch_bounds__(256,1) void k_aspp_mma(
    const float* __restrict__ b1, const float* __restrict__ b2,
    const float* __restrict__ b3)
{
    extern __shared__ char smem[];
    uint32_t sb = smem_u32(smem);
    int tid = threadIdx.x, lane = tid&31, wid = tid>>5;
    int z = blockIdx.z, b = z&3, br = z>>2;
    int D = 1<<br;
    const float* bias = (br==0)?b1:((br==1)?b2:b3);
    int x0 = blockIdx.x*16, y0 = blockIdx.y*8;

    // ---- stage B: both splits, 9 taps, [co][ci] rows swizzled (144KB) ----
    for (int c = tid; c < 9216; c += 256) {
        int ci8 = c&7, co = (c>>3)&63, ts = c>>9;      // ts: 0..17
        int split = ts/9, tap = ts - split*9;
        const __nv_bfloat16* src =
            g_wb + (((size_t)(split*3+br)*9 + tap)*4096 + co*64 + ci8*8);
        uint32_t rel = (uint32_t)(((split*9+tap)*64 + co)*128 + ci8*16);
        cp16(sb + 65536 + swz(rel), src);
    }

    // ---- A tile issue (stage in {0,1}; splits hi/lo; zfill = padding) ----
    auto issueA = [&](int t, int stage){
        int ky = t/3, kx = t - ky*3;
        int dy = (ky-1)*D, dx = (kx-1)*D;
        #pragma unroll
        for (int j = 0; j < 8; j++) {
            int c = tid + j*256;
            int split = c>>10, rem = c&1023, p = rem>>3, ci8 = rem&7;
            int gy = y0 + (p>>4) + dy, gx = x0 + (p&15) + dx;
            bool ok = (gy>=0)&&(gy<HH)&&(gx>=0)&&(gx<WW);
            const __nv_bfloat16* base = split ? g_xl : g_xh;
            const __nv_bfloat16* src =
                base + (((size_t)b*HWW + (ok ? gy*WW+gx : 0))*64 + ci8*8);
            uint32_t rel = (uint32_t)(p*128 + ci8*16);
            cp16z(sb + (stage*2+split)*16384 + swz(rel), src, ok?16:0);
        }
        CP_COMMIT();
    };
    issueA(0, 0);
    issueA(1, 1);

    int m0 = (wid>>1)*32, n0 = (wid&1)*32;
    float d[2][4][4];
    #pragma unroll
    for (int mt = 0; mt < 2; mt++)
        #pragma unroll
        for (int nt = 0; nt < 4; nt++)
            #pragma unroll
            for (int e = 0; e < 4; e++) d[mt][nt][e] = 0.f;

    #pragma unroll 1
    for (int t = 0; t < 9; t++) {
        if (t < 8) asm volatile("cp.async.wait_group 1;" ::: "memory");
        else       asm volatile("cp.async.wait_group 0;" ::: "memory");
        __syncthreads();
        int stage = t & 1;
        uint32_t Ah = sb + (stage*2+0)*16384;
        uint32_t Al = sb + (stage*2+1)*16384;
        uint32_t Bh = sb + 65536 + (uint32_t)(t*64*128);
        uint32_t Bl = sb + 65536 + (uint32_t)((9+t)*64*128);
        #pragma unroll
        for (int ks = 0; ks < 4; ks++) {
            uint32_t ah[2][4], al[2][4], bh[4][2], bl[4][2];
            #pragma unroll
            for (int mt = 0; mt < 2; mt++) {
                uint32_t rel = (uint32_t)((m0 + mt*16 + (lane&15))*128
                                          + ks*32 + (lane>>4)*16);
                ldsm4(ah[mt], Ah + swz(rel));
                ldsm4(al[mt], Al + swz(rel));
            }
            #pragma unroll
            for (int nt2 = 0; nt2 < 2; nt2++) {
                int mid = lane>>3;
                int row = n0 + nt2*16 + (mid>>1)*8 + (lane&7);
                uint32_t rel = (uint32_t)(row*128 + ks*32 + (mid&1)*16);
                uint32_t r4[4];
                ldsm4(r4, Bh + swz(rel));
                bh[nt2*2][0]=r4[0]; bh[nt2*2][1]=r4[1];
                bh[nt2*2+1][0]=r4[2]; bh[nt2*2+1][1]=r4[3];
                ldsm4(r4, Bl + swz(rel));
                bl[nt2*2][0]=r4[0]; bl[nt2*2][1]=r4[1];
                bl[nt2*2+1][0]=r4[2]; bl[nt2*2+1][1]=r4[3];
            }
            #pragma unroll
            for (int mt = 0; mt < 2; mt++)
                #pragma unroll
                for (int nt = 0; nt < 4; nt++) {
                    mma_bf16(d[mt][nt], ah[mt], bh[nt]);
                    mma_bf16(d[mt][nt], ah[mt], bl[nt]);
                    mma_bf16(d[mt][nt], al[mt], bh[nt]);
                }
        }
        __syncthreads();
        if (t < 7) issueA(t+2, stage);
    }

    // ---- epilogue: [px][co] smem transpose -> bias -> LReLU -> bf16 NHWC ----
    float* ep = (float*)smem;              // [128][66]
    #pragma unroll
    for (int mt = 0; mt < 2; mt++)
        #pragma unroll
        for (int nt = 0; nt < 4; nt++) {
            int px = m0 + mt*16 + (lane>>2);
            int co = n0 + nt*8 + (lane&3)*2;
            ep[px*66 + co]       = d[mt][nt][0];
            ep[px*66 + co + 1]   = d[mt][nt][1];
            ep[(px+8)*66 + co]   = d[mt][nt][2];
            ep[(px+8)*66 + co+1] = d[mt][nt][3];
        }
    __syncthreads();
    for (int i = tid; i < 8192; i += 256) {
        int p = i>>6, co = i&63;
        float v = ep[p*66 + co] + __ldg(&bias[co]);
        v = (v >= 0.f) ? v : 0.1f*v;
        size_t gp = (size_t)b*HWW + (size_t)(y0 + (p>>4))*WW + x0 + (p&15);
        __nv_bfloat16 h = __float2bfloat16(v);
        g_rh[gp*192 + br*64 + co] = h;
        g_rl[gp*192 + br*64 + co] = __float2bfloat16(v - __bfloat162float(h));
    }
}

// ---------------------------------------------------------------------------
// Kernel 3: fuse 1x1 192->64 + bias + residual via mma.sync bf16-split
// ---------------------------------------------------------------------------
#define FUSE_SMEM 147456

__global__ __launch_bounds__(256,1) void k_fuse_mma(const float* __restrict__ arb)
{
    extern __shared__ char smem[];
    uint32_t sb = smem_u32(smem);
    int tid = threadIdx.x, lane = tid&31, wid = tid>>5;
    int pxb = blockIdx.x*128;
    int b = pxb/HWW, hw0 = pxb%HWW;

    // stage A: 6 tiles (sub x split) [128px][64ci]  (96KB)
    for (int c = tid; c < 6144; c += 256) {
        int t = c>>10, r = c&1023;         // t = sub*2+split
        int sub = t>>1, split = t&1;
        int p = r>>3, ci8 = r&7;
        const __nv_bfloat16* base = split ? g_rl : g_rh;
        const __nv_bfloat16* src = base + ((size_t)(b*HWW + hw0 + p)*192 + sub*64 + ci8*8);
        cp16(sb + t*16384 + swz((uint32_t)(p*128 + ci8*16)), src);
    }
    // stage B: 6 tiles [64co][64ci] (48KB) at offset 98304
    for (int c = tid; c < 3072; c += 256) {
        int t = c>>9, r = c&511;
        int sub = t>>1, split = t&1;
        int co = r>>3, ci8 = r&7;
        const __nv_bfloat16* src = g_arwb + ((size_t)(split*3+sub)*4096 + co*64 + ci8*8);
        cp16(sb + 98304 + t*8192 + swz((uint32_t)(co*128 + ci8*16)), src);
    }
    CP_COMMIT();
    asm volatile("cp.async.wait_group 0;" ::: "memory");
    __syncthreads();

    int m0 = (wid>>1)*32, n0 = (wid&1)*32;
    float d[2][4][4];
    #pragma unroll
    for (int mt = 0; mt < 2; mt++)
        #pragma unroll
        for (int nt = 0; nt < 4; nt++)
            #pragma unroll
            for (int e = 0; e < 4; e++) d[mt][nt][e] = 0.f;

    #pragma unroll
    for (int sub = 0; sub < 3; sub++) {
        uint32_t Ah = sb + (sub*2+0)*16384;
        uint32_t Al = sb + (sub*2+1)*16384;
        uint32_t Bh = sb + 98304 + (uint32_t)((sub*2+0)*8192);
        uint32_t Bl = sb + 98304 + (uint32_t)((sub*2+1)*8192);
        #pragma unroll
        for (int ks = 0; ks < 4; ks++) {
            uint32_t ah[2][4], al[2][4], bh[4][2], bl[4][2];
            #pragma unroll
            for (int mt = 0; mt < 2; mt++) {
                uint32_t rel = (uint32_t)((m0 + mt*16 + (lane&15))*128
                                          + ks*32 + (lane>>4)*16);
                ldsm4(ah[mt], Ah + swz(rel));
                ldsm4(al[mt], Al + swz(rel));
            }
            #pragma unroll
            for (int nt2 = 0; nt2 < 2; nt2++) {
                int mid = lane>>3;
                int row = n0 + nt2*16 + (mid>>1)*8 + (lane&7);
                uint32_t rel = (uint32_t)(row*128 + ks*32 + (mid&1)*16);
                uint32_t r4[4];
                ldsm4(r4, Bh + swz(rel));
                bh[nt2*2][0]=r4[0]; bh[nt2*2][1]=r4[1];
                bh[nt2*2+1][0]=r4[2]; bh[nt2*2+1][1]=r4[3];
                ldsm4(r4, Bl + swz(rel));
                bl[nt2*2][0]=r4[0]; bl[nt2*2][1]=r4[1];
                bl[nt2*2+1][0]=r4[2]; bl[nt2*2+1][1]=r4[3];
            }
            #pragma unroll
            for (int mt = 0; mt < 2; mt++)
                #pragma unroll
                for (int nt = 0; nt < 4; nt++) {
                    mma_bf16(d[mt][nt], ah[mt], bh[nt]);
                    mma_bf16(d[mt][nt], ah[mt], bl[nt]);
                    mma_bf16(d[mt][nt], al[mt], bh[nt]);
                }
        }
    }

    // epilogue: + bias + residual -> g_t NCHW fp32
    float* ep = (float*)smem;
    __syncthreads();
    #pragma unroll
    for (int mt = 0; mt < 2; mt++)
        #pragma unroll
        for (int nt = 0; nt < 4; nt++) {
            int px = m0 + mt*16 + (lane>>2);
            int co = n0 + nt*8 + (lane&3)*2;
            ep[px*66 + co]       = d[mt][nt][0];
            ep[px*66 + co + 1]   = d[mt][nt][1];
            ep[(px+8)*66 + co]   = d[mt][nt][2];
            ep[(px+8)*66 + co+1] = d[mt][nt][3];
        }
    __syncthreads();
    const float* xb = g_off1 + (size_t)b*64*HWW + hw0;
    float* op = g_t + (size_t)b*64*HWW + hw0;
    for (int i = tid; i < 8192; i += 256) {
        int co = i>>7, p = i&127;
        float v = ep[p*66 + co] + __ldg(&arb[co]) + xb[(size_t)co*HWW + p];
        op[(size_t)co*HWW + p] = v;
    }
}

// ---------------------------------------------------------------------------
// Kernel 3b: offset head 64->18 (SIMT)
// ---------------------------------------------------------------------------
__global__ __launch_bounds__(256,2) void k_head(const float* __restrict__ b02)
{
    __shared__ float w2_s[64*20];
    int tid = threadIdx.x;
    for (int i = tid; i < 64*20; i += 256) {
        int c = i/20, j = i - c*20;
        w2_s[i] = (j < 18) ? g_w02t[c*18 + j] : 0.f;
    }
    __syncthreads();

    int pxb = blockIdx.x*1024;
    int b = pxb/HWW, hw0 = pxb%HWW;

    u64 acc[4][9];
    #pragma unroll
    for (int j = 0; j < 4; j++)
        #pragma unroll
        for (int t = 0; t < 9; t++) acc[j][t] = 0ull;

    const float* tp = g_t + (size_t)b*64*HWW + hw0 + tid;
    for (int c = 0; c < 64; c++) {
        const ulonglong2* wp = (const ulonglong2*)&w2_s[c*20];
        ulonglong2 A = wp[0], B = wp[1], C = wp[2], Dq = wp[3];
        u64 E = *(const u64*)&w2_s[c*20 + 16];
        u64 w9[9] = {A.x,A.y,B.x,B.y,C.x,C.y,Dq.x,Dq.y,E};
        #pragma unroll
        for (int j = 0; j < 4; j++) {
            u64 v = pack2(tp[(size_t)c*HWW + j*256]);
            #pragma unroll
            for (int t = 0; t < 9; t++) acc[j][t] = ffma2(v, w9[t], acc[j][t]);
        }
    }

    float* op = g_off + (size_t)b*18*HWW + hw0 + tid;
    #pragma unroll
    for (int j = 0; j < 4; j++)
        #pragma unroll
        for (int t = 0; t < 9; t++) {
            op[(size_t)(2*t)*HWW + j*256]   = lo2(acc[j][t]) + __ldg(&b02[2*t]);
            op[(size_t)(2*t+1)*HWW + j*256] = hi2(acc[j][t]) + __ldg(&b02[2*t+1]);
        }
}

// ---------------------------------------------------------------------------
// Kernel 4: deformable conv via mma.sync bf16-split.
// Per tap: fp32 bilinear sample (NHWC float4 gathers) -> bf16 hi/lo smem
// -> 3-combo mma. Weights double-buffered cp.async.
// ---------------------------------------------------------------------------
#define DEF_SMEM 69632

__global__ __launch_bounds__(256,1) void k_deform_mma(const float* __restrict__ db,
                                                      float* __restrict__ out)
{
    extern __shared__ char smem[];
    uint32_t sb = smem_u32(smem);
    int tid = threadIdx.x, lane = tid&31, wid = tid>>5;
    int pxb = blockIdx.x*128;
    int b = pxb/HWW, hw0 = pxb%HWW;
    float* pw_s = (float*)(smem + 65536);
    int*   pi_s = (int*)(smem + 65536 + 2048);

    auto issueW = [&](int t){
        int s = t&1;
        #pragma unroll
        for (int j = 0; j < 4; j++) {
            int c = tid + j*256;               // [0,1024)
            int split = c>>9, r = c&511;
            int co = r>>3, ci8 = r&7;
            const __nv_bfloat16* src = g_dwb + ((size_t)(split*9 + t)*4096 + co*64 + ci8*8);
            cp16(sb + 32768 + s*16384 + split*8192 + swz((uint32_t)(co*128 + ci8*16)), src);
        }
        CP_COMMIT();
    };
    issueW(0);

    int m0 = (wid>>1)*32, n0 = (wid&1)*32;
    float d[2][4][4];
    #pragma unroll
    for (int mt = 0; mt < 2; mt++)
        #pragma unroll
        for (int nt = 0; nt < 4; nt++)
            #pragma unroll
            for (int e = 0; e < 4; e++) d[mt][nt][e] = 0.f;

    const float* xb = g_xt + (size_t)b*HWW*64;

    #pragma unroll 1
    for (int k = 0; k < 9; k++) {
        // per-pixel bilinear params for tap k
        if (tid < 128) {
            int px = tid, hw = hw0 + px;
            int h = hw/WW, w = hw - h*WW;
            int ky = k/3, kx = k - ky*3;
            const float* offb = g_off + (size_t)b*18*HWW + hw;
            float py  = (float)(h - 1 + ky) + offb[(size_t)(2*k)*HWW];
            float pxf = (float)(w - 1 + kx) + offb[(size_t)(2*k+1)*HWW];
            float fy = floorf(py), fx = floorf(pxf);
            int iy = (int)fy, ix = (int)fx;
            float wy = py - fy, wx = pxf - fx;
            bool vy0 = (iy   >= 0 && iy   < HH);
            bool vy1 = (iy+1 >= 0 && iy+1 < HH);
            bool vx0 = (ix   >= 0 && ix   < WW);
            bool vx1 = (ix+1 >= 0 && ix+1 < WW);
            float w00 = (1.f-wy)*(1.f-wx); if (!(vy0&&vx0)) w00 = 0.f;
            float w01 = (1.f-wy)*wx;       if (!(vy0&&vx1)) w01 = 0.f;
            float w10 = wy*(1.f-wx);       if (!(vy1&&vx0)) w10 = 0.f;
            float w11 = wy*wx;             if (!(vy1&&vx1)) w11 = 0.f;
            int cy0 = min(max(iy,0),HH-1),   cy1 = min(max(iy+1,0),HH-1);
            int cx0 = min(max(ix,0),WW-1),   cx1 = min(max(ix+1,0),WW-1);
            pw_s[px*4+0] = w00; pw_s[px*4+1] = w01;
            pw_s[px*4+2] = w10; pw_s[px*4+3] = w11;
            pi_s[px*4+0] = (cy0*WW + cx0)*64; pi_s[px*4+1] = (cy0*WW + cx1)*64;
            pi_s[px*4+2] = (cy1*WW + cx0)*64; pi_s[px*4+3] = (cy1*WW + cx1)*64;
        }
        if (k < 8) issueW(k+1);
        __syncthreads();   // params visible; samp buffer free (prev mma sync'd)

        // sample + split to bf16 hi/lo smem tiles
        {
            int px = tid>>1, ch0 = (tid&1)*32;
            float w00 = pw_s[px*4+0], w01v = pw_s[px*4+1];
            float w10 = pw_s[px*4+2], w11  = pw_s[px*4+3];
            int i00 = pi_s[px*4+0], i01 = pi_s[px*4+1];
            int i10 = pi_s[px*4+2], i11 = pi_s[px*4+3];
            #pragma unroll
            for (int q = 0; q < 8; q++) {
                int c = ch0 + q*4;
                float4 A = *(const float4*)(xb + i00 + c);
                float4 Bq= *(const float4*)(xb + i01 + c);
                float4 C = *(const float4*)(xb + i10 + c);
                float4 Dq= *(const float4*)(xb + i11 + c);
                float s0 = w00*A.x + w01v*Bq.x + w10*C.x + w11*Dq.x;
                float s1 = w00*A.y + w01v*Bq.y + w10*C.y + w11*Dq.y;
                float s2 = w00*A.z + w01v*Bq.z + w10*C.z + w11*Dq.z;
                float s3 = w00*A.w + w01v*Bq.w + w10*C.w + w11*Dq.w;
                __nv_bfloat16 h0 = __float2bfloat16(s0);
                __nv_bfloat16 h1 = __float2bfloat16(s1);
                __nv_bfloat16 h2 = __float2bfloat16(s2);
                __nv_bfloat16 h3 = __float2bfloat16(s3);
                uint32_t hp0 = (uint32_t)__bfloat16_as_ushort(h1)<<16 | __bfloat16_as_ushort(h0);
                uint32_t hp1 = (uint32_t)__bfloat16_as_ushort(h3)<<16 | __bfloat16_as_ushort(h2);
                __nv_bfloat162 lp0 = __floats2bfloat162_rn(s0 - __bfloat162float(h0),
                                                           s1 - __bfloat162float(h1));
                __nv_bfloat162 lp1 = __floats2bfloat162_rn(s2 - __bfloat162float(h2),
                                                           s3 - __bfloat162float(h3));
                uint32_t rel = (uint32_t)(px*128 + c*2);
                *(uint32_t*)(smem + swz(rel))          = hp0;
                *(uint32_t*)(smem + swz(rel+4))        = hp1;
                *(uint32_t*)(smem + 16384 + swz(rel))  = *(uint32_t*)&lp0;
                *(uint32_t*)(smem + 16384 + swz(rel+4))= *(uint32_t*)&lp1;
            }
        }
        if (k < 8) asm volatile("cp.async.wait_group 1;" ::: "memory");
        else       asm volatile("cp.async.wait_group 0;" ::: "memory");
        __syncthreads();

        uint32_t Ah = sb, Al = sb + 16384;
        uint32_t Bh = sb + 32768 + (uint32_t)((k&1)*16384);
        uint32_t Bl = Bh + 8192;
        #pragma unroll
        for (int ks = 0; ks < 4; ks++) {
            uint32_t ah[2][4], al[2][4], bh[4][2], bl[4][2];
            #pragma unroll
            for (int mt = 0; mt < 2; mt++) {
                uint32_t rel = (uint32_t)((m0 + mt*16 + (lane&15))*128
                                          + ks*32 + (lane>>4)*16);
                ldsm4(ah[mt], Ah + swz(rel));
                ldsm4(al[mt], Al + swz(rel));
            }
            #pragma unroll
            for (int nt2 = 0; nt2 < 2; nt2++) {
                int mid = lane>>3;
                int row = n0 + nt2*16 + (mid>>1)*8 + (lane&7);
                uint32_t rel = (uint32_t)(row*128 + ks*32 + (mid&1)*16);
                uint32_t r4[4];
                ldsm4(r4, Bh + swz(rel));
                bh[nt2*2][0]=r4[0]; bh[nt2*2][1]=r4[1];
                bh[nt2*2+1][0]=r4[2]; bh[nt2*2+1][1]=r4[3];
                ldsm4(r4, Bl + swz(rel));
                bl[nt2*2][0]=r4[0]; bl[nt2*2][1]=r4[1];
                bl[nt2*2+1][0]=r4[2]; bl[nt2*2+1][1]=r4[3];
            }
            #pragma unroll
            for (int mt = 0; mt < 2; mt++)
                #pragma unroll
                for (int nt = 0; nt < 4; nt++) {
                    mma_bf16(d[mt][nt], ah[mt], bh[nt]);
                    mma_bf16(d[mt][nt], ah[mt], bl[nt]);
                    mma_bf16(d[mt][nt], al[mt], bh[nt]);
                }
        }
        __syncthreads();   // mma consumed before next tap overwrites samp
    }

    // epilogue -> out NCHW fp32 + bias
    float* ep = (float*)smem;
    #pragma unroll
    for (int mt = 0; mt < 2; mt++)
        #pragma unroll
        for (int nt = 0; nt < 4; nt++) {
            int px = m0 + mt*16 + (lane>>2);
            int co = n0 + nt*8 + (lane&3)*2;
            ep[px*66 + co]       = d[mt][nt][0];
            ep[px*66 + co + 1]   = d[mt][nt][1];
            ep[(px+8)*66 + co]   = d[mt][nt][2];
            ep[(px+8)*66 + co+1] = d[mt][nt][3];
        }
    __syncthreads();
    float* op = out + (size_t)b*64*HWW + hw0;
    for (int i = tid; i < 8192; i += 256) {
        int co = i>>7, p = i&127;
        op[(size_t)co*HWW + p] = ep[p*66 + co] + __ldg(&db[co]);
    }
}

// ===========================================================================
extern "C" void kernel_launch(void* const* d_in, const int* in_sizes, int n_in,
                              void* d_out, int out_size)
{
    const float* in_aux = (const float*)d_in[0];
    const float* in_ref = (const float*)d_in[1];
    const float* w01    = (const float*)d_in[2];
    const float* b01    = (const float*)d_in[3];
    const float* a1w    = (const float*)d_in[4];
    const float* a1b    = (const float*)d_in[5];
    const float* a2w    = (const float*)d_in[6];
    const float* a2b    = (const float*)d_in[7];
    const float* a3w    = (const float*)d_in[8];
    const float* a3b    = (const float*)d_in[9];
    const float* arw    = (const float*)d_in[10];
    const float* arb    = (const float*)d_in[11];
    const float* w02    = (const float*)d_in[12];
    const float* b02    = (const float*)d_in[13];
    const float* dwp    = (const float*)d_in[14];
    const float* dbp    = (const float*)d_in[15];
    float* out = (float*)d_out;

    static int s_inited = 0;
    if (!s_inited) {
        cudaFuncSetAttribute(k_aspp_mma,   cudaFuncAttributeMaxDynamicSharedMemorySize, ASPP_SMEM);
        cudaFuncSetAttribute(k_fuse_mma,   cudaFuncAttributeMaxDynamicSharedMemorySize, FUSE_SMEM);
        cudaFuncSetAttribute(k_deform_mma, cudaFuncAttributeMaxDynamicSharedMemorySize, DEF_SMEM);
        s_inited = 1;
    }

    k_prep<<<1285, 256>>>(w01, a1w, a2w, a3w, arw, w02, dwp);
    k_nhwc<<<dim3(800, 4), 256>>>(in_aux);
    k_conv1<<<400, 256>>>(in_aux, in_ref, b01);
    k_split<<<dim3(800, 4), 256>>>();

    dim3 ga(10, 20, 12);
    k_aspp_mma<<<ga, 256, ASPP_SMEM>>>(a1b, a2b, a3b);

    k_fuse_mma<<<800, 256, FUSE_SMEM>>>(arb);
    k_head<<<100, 256>>>(b02);
    k_deform_mma<<<800, 256, DEF_SMEM>>>(dbp, out);
}

// round 8
// speedup vs baseline: 2.5761x; 1.1669x over previous
#include <cuda_runtime.h>
#include <cuda_bf16.h>
#include <math.h>
#include <stdint.h>

#define HH 160
#define WW 160
#define HWW (160*160)
#define BB 4

typedef unsigned long long u64;

// ======================= PTX helpers (base ISA only) ========================
__device__ __forceinline__ u64 ffma2(u64 a, u64 b, u64 c){
    u64 d; asm("fma.rn.f32x2 %0, %1, %2, %3;" : "=l"(d) : "l"(a), "l"(b), "l"(c)); return d;
}
__device__ __forceinline__ u64 pack2(float x){
    u64 d; asm("mov.b64 %0, {%1, %1};" : "=l"(d) : "f"(x), "f"(x)); return d;
}
__device__ __forceinline__ float lo2(u64 a){ return __uint_as_float((unsigned)a); }
__device__ __forceinline__ float hi2(u64 a){ return __uint_as_float((unsigned)(a>>32)); }

__device__ __forceinline__ uint32_t smem_u32(const void* p){
    uint32_t a; asm("{ .reg .u64 t; cvta.to.shared.u64 t, %1; cvt.u32.u64 %0, t; }" : "=r"(a) : "l"(p));
    return a;
}
__device__ __forceinline__ void cp16(uint32_t dst, const void* src){
    asm volatile("cp.async.ca.shared.global [%0], [%1], 16;" :: "r"(dst), "l"(src) : "memory");
}
__device__ __forceinline__ void cp16z(uint32_t dst, const void* src, int sz){
    asm volatile("cp.async.ca.shared.global [%0], [%1], 16, %2;" :: "r"(dst), "l"(src), "r"(sz) : "memory");
}
#define CP_COMMIT() asm volatile("cp.async.commit_group;" ::: "memory")

__device__ __forceinline__ void ldsm4(uint32_t* r, uint32_t a){
    asm volatile("ldmatrix.sync.aligned.m8n8.x4.shared.b16 {%0,%1,%2,%3}, [%4];"
      : "=r"(r[0]),"=r"(r[1]),"=r"(r[2]),"=r"(r[3]) : "r"(a));
}
__device__ __forceinline__ void mma_bf16(float* d, const uint32_t* a, const uint32_t* b){
    asm volatile("mma.sync.aligned.m16n8k16.row.col.f32.bf16.bf16.f32 "
      "{%0,%1,%2,%3}, {%4,%5,%6,%7}, {%8,%9}, {%0,%1,%2,%3};"
      : "+f"(d[0]),"+f"(d[1]),"+f"(d[2]),"+f"(d[3])
      : "r"(a[0]),"r"(a[1]),"r"(a[2]),"r"(a[3]),"r"(b[0]),"r"(b[1]));
}
__device__ __forceinline__ uint32_t swz(uint32_t r){ return r ^ ((r>>3)&0x70); }

// ================= device-global scratch (no allocation allowed) ============
__device__ __align__(16) float g_off1[BB*64*HWW];        // conv1 out NCHW (residual)
__device__ __align__(16) float g_t  [BB*64*HWW];         // fused features NCHW
__device__ __align__(16) float g_off[BB*18*HWW];         // offsets NCHW
__device__ __align__(16) float g_xt [BB*HWW*64];         // in_aux NHWC fp32 (deform)
__device__ __align__(16) __nv_bfloat16 g_inh[(size_t)BB*HWW*128]; // concat inputs NHWC hi
__device__ __align__(16) __nv_bfloat16 g_inl[(size_t)BB*HWW*128]; // concat inputs NHWC lo
__device__ __align__(16) __nv_bfloat16 g_xh[BB*HWW*64];  // conv1 out NHWC bf16 hi
__device__ __align__(16) __nv_bfloat16 g_xl[BB*HWW*64];  // conv1 out NHWC bf16 lo
__device__ __align__(16) __nv_bfloat16 g_rh[(size_t)BB*HWW*192]; // concat NHWC hi
__device__ __align__(16) __nv_bfloat16 g_rl[(size_t)BB*HWW*192]; // concat NHWC lo
__device__ __align__(16) __nv_bfloat16 g_wb  [2*3*9*64*64]; // ASPP W [split][br][tap][co][ci]
__device__ __align__(16) __nv_bfloat16 g_arwb[2*3*64*64];   // fuse W [split][sub][co][ci]
__device__ __align__(16) __nv_bfloat16 g_dwb [2*9*64*64];   // deform W [split][tap][co][ci]
__device__ __align__(16) __nv_bfloat16 g_w01b[2*2*64*64];   // conv1 W [split][half][co][ci]
__device__ float g_w02t[64*18];

// ---------------------------------------------------------------------------
// prep: weight transposes + bf16 splits
// ---------------------------------------------------------------------------
__global__ void k_prep(const float* __restrict__ w01, const float* __restrict__ a1w,
                       const float* __restrict__ a2w, const float* __restrict__ a3w,
                       const float* __restrict__ arw, const float* __restrict__ w02,
                       const float* __restrict__ dw)
{
    int i = blockIdx.x*256 + threadIdx.x;
    if (i < 1152) { int c = i/18, j = i - c*18; g_w02t[i] = w02[j*64 + c]; return; }
    i -= 1152;
    if (i < 221184) {
        int s  = i / 110592;
        int q  = i % 110592;
        int br = q / 36864;
        int q2 = q % 36864;
        int tap = q2 / 4096;
        int r   = q2 % 4096;
        int co = r >> 6, ci = r & 63;
        const float* w = (br==0)?a1w:(br==1)?a2w:a3w;
        float v = w[(co*64+ci)*9 + tap];
        __nv_bfloat16 h = __float2bfloat16(v);
        g_wb[i] = (s==0) ? h : __float2bfloat16(v - __bfloat162float(h));
        return;
    }
    i -= 221184;
    if (i < 24576) {
        int s = i / 12288, q = i % 12288;
        int sub = q / 4096, r = q % 4096;
        int co = r >> 6, ci = r & 63;
        float v = arw[co*192 + sub*64 + ci];
        __nv_bfloat16 h = __float2bfloat16(v);
        g_arwb[i] = (s==0) ? h : __float2bfloat16(v - __bfloat162float(h));
        return;
    }
    i -= 24576;
    if (i < 73728) {
        int s = i / 36864, q = i % 36864;
        int tap = q / 4096, r = q % 4096;
        int co = r >> 6, ci = r & 63;
        float v = dw[(co*64+ci)*9 + tap];
        __nv_bfloat16 h = __float2bfloat16(v);
        g_dwb[i] = (s==0) ? h : __float2bfloat16(v - __bfloat162float(h));
        return;
    }
    i -= 73728;
    if (i < 16384) {                       // FIXED: 2 splits x 2 halves x 64 x 64
        int s = i / 8192, q = i % 8192;
        int half = q / 4096, r = q % 4096;
        int co = r >> 6, ci = r & 63;
        float v = w01[co*128 + half*64 + ci];
        __nv_bfloat16 h = __float2bfloat16(v);
        g_w01b[i] = (s==0) ? h : __float2bfloat16(v - __bfloat162float(h));
    }
}

// ---------------------------------------------------------------------------
// input prep: in_aux/in_ref NCHW fp32 -> NHWC bf16 hi/lo concat (128ch) +
// in_aux NHWC fp32 (deform sampling)
// ---------------------------------------------------------------------------
__global__ void k_splitin(const float* __restrict__ aux, const float* __restrict__ refi)
{
    __shared__ float sm[64][33];
    int b = blockIdx.y;
    int hw0 = blockIdx.x*32;
    int tid = threadIdx.x;
    int hl = tid&31, cl = tid>>5;
    int c2 = tid&63, hr = tid>>6;

    #pragma unroll
    for (int half = 0; half < 2; half++) {
        const float* xp = (half ? refi : aux) + (size_t)b*64*HWW;
        if (half) __syncthreads();
        #pragma unroll
        for (int p = 0; p < 8; p++) { int c = cl + p*8; sm[c][hl] = xp[(size_t)c*HWW + hw0 + hl]; }
        __syncthreads();
        #pragma unroll
        for (int p = 0; p < 8; p++) {
            int hh = hr + p*4;
            float v = sm[c2][hh];
            __nv_bfloat16 h = __float2bfloat16(v);
            size_t gp = (size_t)b*HWW + hw0 + hh;
            g_inh[gp*128 + half*64 + c2] = h;
            g_inl[gp*128 + half*64 + c2] = __float2bfloat16(v - __bfloat162float(h));
            if (half == 0) g_xt[gp*64 + c2] = v;
        }
    }
}

// ---------------------------------------------------------------------------
// Kernel 1: conv1 1x1 128->64 + LReLU via mma. Epilogue -> g_off1 (NCHW fp32)
// + g_xh/g_xl (NHWC bf16 hi/lo). 96KB smem, 2 CTAs/SM.
// ---------------------------------------------------------------------------
#define C1_SMEM 98304

__global__ __launch_bounds__(256,2) void k_conv1_mma(const float* __restrict__ b01)
{
    extern __shared__ char smem[];
    uint32_t sb = smem_u32(smem);
    int tid = threadIdx.x, lane = tid&31, wid = tid>>5;
    int pxb = blockIdx.x*128;
    int b = pxb/HWW, hw0 = pxb%HWW;

    // stage A: 4 tiles (half*2+split) [128px][64ci] (64KB)
    for (int c = tid; c < 4096; c += 256) {
        int t = c>>10, r = c&1023;
        int half = t>>1, split = t&1;
        int p = r>>3, ci8 = r&7;
        const __nv_bfloat16* base = split ? g_inl : g_inh;
        const __nv_bfloat16* src = base + ((size_t)(b*HWW + hw0 + p)*128 + half*64 + ci8*8);
        cp16(sb + t*16384 + swz((uint32_t)(p*128 + ci8*16)), src);
    }
    // stage B: 4 tiles [64co][64ci] (32KB) at 65536
    for (int c = tid; c < 2048; c += 256) {
        int t = c>>9, r = c&511;
        int half = t>>1, split = t&1;
        int co = r>>3, ci8 = r&7;
        const __nv_bfloat16* src = g_w01b + ((size_t)(split*2+half)*4096 + co*64 + ci8*8);
        cp16(sb + 65536 + t*8192 + swz((uint32_t)(co*128 + ci8*16)), src);
    }
    CP_COMMIT();
    asm volatile("cp.async.wait_group 0;" ::: "memory");
    __syncthreads();

    int m0 = (wid>>1)*32, n0 = (wid&1)*32;
    float d[2][4][4];
    #pragma unroll
    for (int mt = 0; mt < 2; mt++)
        #pragma unroll
        for (int nt = 0; nt < 4; nt++)
            #pragma unroll
            for (int e = 0; e < 4; e++) d[mt][nt][e] = 0.f;

    #pragma unroll
    for (int half = 0; half < 2; half++) {
        uint32_t Ah = sb + (half*2+0)*16384;
        uint32_t Al = sb + (half*2+1)*16384;
        uint32_t Bh = sb + 65536 + (uint32_t)((half*2+0)*8192);
        uint32_t Bl = sb + 65536 + (uint32_t)((half*2+1)*8192);
        #pragma unroll
        for (int ks = 0; ks < 4; ks++) {
            uint32_t ah[2][4], al[2][4], bh[4][2], bl[4][2];
            #pragma unroll
            for (int mt = 0; mt < 2; mt++) {
                uint32_t rel = (uint32_t)((m0 + mt*16 + (lane&15))*128
                                          + ks*32 + (lane>>4)*16);
                ldsm4(ah[mt], Ah + swz(rel));
                ldsm4(al[mt], Al + swz(rel));
            }
            #pragma unroll
            for (int nt2 = 0; nt2 < 2; nt2++) {
                int mid = lane>>3;
                int row = n0 + nt2*16 + (mid>>1)*8 + (lane&7);
                uint32_t rel = (uint32_t)(row*128 + ks*32 + (mid&1)*16);
                uint32_t r4[4];
                ldsm4(r4, Bh + swz(rel));
                bh[nt2*2][0]=r4[0]; bh[nt2*2][1]=r4[1];
                bh[nt2*2+1][0]=r4[2]; bh[nt2*2+1][1]=r4[3];
                ldsm4(r4, Bl + swz(rel));
                bl[nt2*2][0]=r4[0]; bl[nt2*2][1]=r4[1];
                bl[nt2*2+1][0]=r4[2]; bl[nt2*2+1][1]=r4[3];
            }
            #pragma unroll
            for (int mt = 0; mt < 2; mt++)
                #pragma unroll
                for (int nt = 0; nt < 4; nt++) {
                    mma_bf16(d[mt][nt], ah[mt], bh[nt]);
                    mma_bf16(d[mt][nt], ah[mt], bl[nt]);
                    mma_bf16(d[mt][nt], al[mt], bh[nt]);
                }
        }
    }

    float* ep = (float*)smem;
    __syncthreads();
    #pragma unroll
    for (int mt = 0; mt < 2; mt++)
        #pragma unroll
        for (int nt = 0; nt < 4; nt++) {
            int px = m0 + mt*16 + (lane>>2);
            int co = n0 + nt*8 + (lane&3)*2;
            ep[px*66 + co]       = d[mt][nt][0];
            ep[px*66 + co + 1]   = d[mt][nt][1];
            ep[(px+8)*66 + co]   = d[mt][nt][2];
            ep[(px+8)*66 + co+1] = d[mt][nt][3];
        }
    __syncthreads();
    float* op = g_off1 + (size_t)b*64*HWW + hw0;
    for (int i = tid; i < 8192; i += 256) {
        int co = i>>7, p = i&127;
        float v = ep[p*66 + co] + __ldg(&b01[co]);
        v = (v >= 0.f) ? v : 0.1f*v;
        op[(size_t)co*HWW + p] = v;
    }
    for (int i = tid; i < 8192; i += 256) {
        int p = i>>6, co = i&63;
        float v = ep[p*66 + co] + __ldg(&b01[co]);
        v = (v >= 0.f) ? v : 0.1f*v;
        size_t gp = (size_t)b*HWW + hw0 + p;
        __nv_bfloat16 h = __float2bfloat16(v);
        g_xh[gp*64 + co] = h;
        g_xl[gp*64 + co] = __float2bfloat16(v - __bfloat162float(h));
    }
}

// ---------------------------------------------------------------------------
// Kernel 2: ASPP dilated 3x3 via mma.sync bf16-split. 96KB smem (A+B both
// double-buffered per tap) -> 2 CTAs/SM. Epilogue -> bf16 hi/lo NHWC concat.
// ---------------------------------------------------------------------------
#define ASPP_SMEM 98304

__global__ __launch_bounds__(256,2) void k_aspp_mma(
    const float* __restrict__ b1, const float* __restrict__ b2,
    const float* __restrict__ b3)
{
    extern __shared__ char smem[];
    uint32_t sb = smem_u32(smem);
    int tid = threadIdx.x, lane = tid&31, wid = tid>>5;
    int z = blockIdx.z, b = z&3, br = z>>2;
    int D = 1<<br;
    const float* bias = (br==0)?b1:((br==1)?b2:b3);
    int x0 = blockIdx.x*16, y0 = blockIdx.y*8;

    // A stage s split p: sb + (s*2+p)*16384 ; B stage s split p: sb+65536+(s*2+p)*8192
    auto issueT = [&](int t, int stage){
        int ky = t/3, kx = t - ky*3;
        int dy = (ky-1)*D, dx = (kx-1)*D;
        #pragma unroll
        for (int j = 0; j < 8; j++) {
            int c = tid + j*256;
            int split = c>>10, rem = c&1023, p = rem>>3, ci8 = rem&7;
            int gy = y0 + (p>>4) + dy, gx = x0 + (p&15) + dx;
            bool ok = (gy>=0)&&(gy<HH)&&(gx>=0)&&(gx<WW);
            const __nv_bfloat16* base = split ? g_xl : g_xh;
            const __nv_bfloat16* src =
                base + (((size_t)b*HWW + (ok ? gy*WW+gx : 0))*64 + ci8*8);
            uint32_t rel = (uint32_t)(p*128 + ci8*16);
            cp16z(sb + (stage*2+split)*16384 + swz(rel), src, ok?16:0);
        }
        #pragma unroll
        for (int j = 0; j < 4; j++) {
            int c = tid + j*256;                // [0,1024)
            int split = c>>9, r = c&511;
            int co = r>>3, ci8 = r&7;
            const __nv_bfloat16* src =
                g_wb + (((size_t)(split*3+br)*9 + t)*4096 + co*64 + ci8*8);
            cp16(sb + 65536 + (stage*2+split)*8192 + swz((uint32_t)(co*128 + ci8*16)), src);
        }
        CP_COMMIT();
    };
    issueT(0, 0);
    issueT(1, 1);

    int m0 = (wid>>1)*32, n0 = (wid&1)*32;
    float d[2][4][4];
    #pragma unroll
    for (int mt = 0; mt < 2; mt++)
        #pragma unroll
        for (int nt = 0; nt < 4; nt++)
            #pragma unroll
            for (int e = 0; e < 4; e++) d[mt][nt][e] = 0.f;

    #pragma unroll 1
    for (int t = 0; t < 9; t++) {
        if (t < 8) asm volatile("cp.async.wait_group 1;" ::: "memory");
        else       asm volatile("cp.async.wait_group 0;" ::: "memory");
        __syncthreads();
        int stage = t & 1;
        uint32_t Ah = sb + (stage*2+0)*16384;
        uint32_t Al = sb + (stage*2+1)*16384;
        uint32_t Bh = sb + 65536 + (uint32_t)((stage*2+0)*8192);
        uint32_t Bl = sb + 65536 + (uint32_t)((stage*2+1)*8192);
        #pragma unroll
        for (int ks = 0; ks < 4; ks++) {
            uint32_t ah[2][4], al[2][4], bh[4][2], bl[4][2];
            #pragma unroll
            for (int mt = 0; mt < 2; mt++) {
                uint32_t rel = (uint32_t)((m0 + mt*16 + (lane&15))*128
                                          + ks*32 + (lane>>4)*16);
                ldsm4(ah[mt], Ah + swz(rel));
                ldsm4(al[mt], Al + swz(rel));
            }
            #pragma unroll
            for (int nt2 = 0; nt2 < 2; nt2++) {
                int mid = lane>>3;
                int row = n0 + nt2*16 + (mid>>1)*8 + (lane&7);
                uint32_t rel = (uint32_t)(row*128 + ks*32 + (mid&1)*16);
                uint32_t r4[4];
                ldsm4(r4, Bh + swz(rel));
                bh[nt2*2][0]=r4[0]; bh[nt2*2][1]=r4[1];
                bh[nt2*2+1][0]=r4[2]; bh[nt2*2+1][1]=r4[3];
                ldsm4(r4, Bl + swz(rel));
                bl[nt2*2][0]=r4[0]; bl[nt2*2][1]=r4[1];
                bl[nt2*2+1][0]=r4[2]; bl[nt2*2+1][1]=r4[3];
            }
            #pragma unroll
            for (int mt = 0; mt < 2; mt++)
                #pragma unroll
                for (int nt = 0; nt < 4; nt++) {
                    mma_bf16(d[mt][nt], ah[mt], bh[nt]);
                    mma_bf16(d[mt][nt], ah[mt], bl[nt]);
                    mma_bf16(d[mt][nt], al[mt], bh[nt]);
                }
        }
        __syncthreads();
        if (t < 7) issueT(t+2, stage);
    }

    // epilogue: [px][co] smem -> bias -> LReLU -> bf16 hi/lo NHWC concat
    float* ep = (float*)smem;              // [128][66]
    #pragma unroll
    for (int mt = 0; mt < 2; mt++)
        #pragma unroll
        for (int nt = 0; nt < 4; nt++) {
            int px = m0 + mt*16 + (lane>>2);
            int co = n0 + nt*8 + (lane&3)*2;
            ep[px*66 + co]       = d[mt][nt][0];
            ep[px*66 + co + 1]   = d[mt][nt][1];
            ep[(px+8)*66 + co]   = d[mt][nt][2];
            ep[(px+8)*66 + co+1] = d[mt][nt][3];
        }
    __syncthreads();
    for (int i = tid; i < 8192; i += 256) {
        int p = i>>6, co = i&63;
        float v = ep[p*66 + co] + __ldg(&bias[co]);
        v = (v >= 0.f) ? v : 0.1f*v;
        size_t gp = (size_t)b*HWW + (size_t)(y0 + (p>>4))*WW + x0 + (p&15);
        __nv_bfloat16 h = __float2bfloat16(v);
        g_rh[gp*192 + br*64 + co] = h;
        g_rl[gp*192 + br*64 + co] = __float2bfloat16(v - __bfloat162float(h));
    }
}

// ---------------------------------------------------------------------------
// Kernel 3: fuse 1x1 192->64 + bias + residual via mma (112KB smem)
// ---------------------------------------------------------------------------
#define FUSE_SMEM 114688

__global__ __launch_bounds__(256,2) void k_fuse_mma(const float* __restrict__ arb)
{
    extern __shared__ char smem[];
    uint32_t sb = smem_u32(smem);
    int tid = threadIdx.x, lane = tid&31, wid = tid>>5;
    int pxb = blockIdx.x*128;
    int b = pxb/HWW, hw0 = pxb%HWW;

    // A stage s: sb + (s*2+split)*16384 (64KB); B: 6 tiles at sb+65536 (48KB)
    auto issueA = [&](int sub, int stage){
        #pragma unroll
        for (int j = 0; j < 8; j++) {
            int c = tid + j*256;                    // [0,2048)
            int split = c>>10, r = c&1023;
            int p = r>>3, ci8 = r&7;
            const __nv_bfloat16* base = split ? g_rl : g_rh;
            const __nv_bfloat16* src = base + ((size_t)(b*HWW + hw0 + p)*192 + sub*64 + ci8*8);
            cp16(sb + (stage*2+split)*16384 + swz((uint32_t)(p*128 + ci8*16)), src);
        }
        CP_COMMIT();
    };
    // stage B (once) with first A
    for (int c = tid; c < 3072; c += 256) {
        int t = c>>9, r = c&511;
        int sub = t>>1, split = t&1;
        int co = r>>3, ci8 = r&7;
        const __nv_bfloat16* src = g_arwb + ((size_t)(split*3+sub)*4096 + co*64 + ci8*8);
        cp16(sb + 65536 + t*8192 + swz((uint32_t)(co*128 + ci8*16)), src);
    }
    issueA(0, 0);
    issueA(1, 1);

    int m0 = (wid>>1)*32, n0 = (wid&1)*32;
    float d[2][4][4];
    #pragma unroll
    for (int mt = 0; mt < 2; mt++)
        #pragma unroll
        for (int nt = 0; nt < 4; nt++)
            #pragma unroll
            for (int e = 0; e < 4; e++) d[mt][nt][e] = 0.f;

    #pragma unroll 1
    for (int sub = 0; sub < 3; sub++) {
        if (sub < 2) asm volatile("cp.async.wait_group 1;" ::: "memory");
        else         asm volatile("cp.async.wait_group 0;" ::: "memory");
        __syncthreads();
        int stage = sub & 1;
        uint32_t Ah = sb + (stage*2+0)*16384;
        uint32_t Al = sb + (stage*2+1)*16384;
        uint32_t Bh = sb + 65536 + (uint32_t)((sub*2+0)*8192);
        uint32_t Bl = sb + 65536 + (uint32_t)((sub*2+1)*8192);
        #pragma unroll
        for (int ks = 0; ks < 4; ks++) {
            uint32_t ah[2][4], al[2][4], bh[4][2], bl[4][2];
            #pragma unroll
            for (int mt = 0; mt < 2; mt++) {
                uint32_t rel = (uint32_t)((m0 + mt*16 + (lane&15))*128
                                          + ks*32 + (lane>>4)*16);
                ldsm4(ah[mt], Ah + swz(rel));
                ldsm4(al[mt], Al + swz(rel));
            }
            #pragma unroll
            for (int nt2 = 0; nt2 < 2; nt2++) {
                int mid = lane>>3;
                int row = n0 + nt2*16 + (mid>>1)*8 + (lane&7);
                uint32_t rel = (uint32_t)(row*128 + ks*32 + (mid&1)*16);
                uint32_t r4[4];
                ldsm4(r4, Bh + swz(rel));
                bh[nt2*2][0]=r4[0]; bh[nt2*2][1]=r4[1];
                bh[nt2*2+1][0]=r4[2]; bh[nt2*2+1][1]=r4[3];
                ldsm4(r4, Bl + swz(rel));
                bl[nt2*2][0]=r4[0]; bl[nt2*2][1]=r4[1];
                bl[nt2*2+1][0]=r4[2]; bl[nt2*2+1][1]=r4[3];
            }
            #pragma unroll
            for (int mt = 0; mt < 2; mt++)
                #pragma unroll
                for (int nt = 0; nt < 4; nt++) {
                    mma_bf16(d[mt][nt], ah[mt], bh[nt]);
                    mma_bf16(d[mt][nt], ah[mt], bl[nt]);
                    mma_bf16(d[mt][nt], al[mt], bh[nt]);
                }
        }
        __syncthreads();
        if (sub < 1) issueA(sub+2, stage);
    }

    // epilogue: + bias + residual -> g_t NCHW fp32
    float* ep = (float*)smem;
    #pragma unroll
    for (int mt = 0; mt < 2; mt++)
        #pragma unroll
        for (int nt = 0; nt < 4; nt++) {
            int px = m0 + mt*16 + (lane>>2);
            int co = n0 + nt*8 + (lane&3)*2;
            ep[px*66 + co]       = d[mt][nt][0];
            ep[px*66 + co + 1]   = d[mt][nt][1];
            ep[(px+8)*66 + co]   = d[mt][nt][2];
            ep[(px+8)*66 + co+1] = d[mt][nt][3];
        }
    __syncthreads();
    const float* xb = g_off1 + (size_t)b*64*HWW + hw0;
    float* op = g_t + (size_t)b*64*HWW + hw0;
    for (int i = tid; i < 8192; i += 256) {
        int co = i>>7, p = i&127;
        float v = ep[p*66 + co] + __ldg(&arb[co]) + xb[(size_t)co*HWW + p];
        op[(size_t)co*HWW + p] = v;
    }
}

// ---------------------------------------------------------------------------
// Kernel 3b: offset head 64->18 (SIMT)
// ---------------------------------------------------------------------------
__global__ __launch_bounds__(256,2) void k_head(const float* __restrict__ b02)
{
    __shared__ float w2_s[64*20];
    int tid = threadIdx.x;
    for (int i = tid; i < 64*20; i += 256) {
        int c = i/20, j = i - c*20;
        w2_s[i] = (j < 18) ? g_w02t[c*18 + j] : 0.f;
    }
    __syncthreads();

    int pxb = blockIdx.x*1024;
    int b = pxb/HWW, hw0 = pxb%HWW;

    u64 acc[4][9];
    #pragma unroll
    for (int j = 0; j < 4; j++)
        #pragma unroll
        for (int t = 0; t < 9; t++) acc[j][t] = 0ull;

    const float* tp = g_t + (size_t)b*64*HWW + hw0 + tid;
    for (int c = 0; c < 64; c++) {
        const ulonglong2* wp = (const ulonglong2*)&w2_s[c*20];
        ulonglong2 A = wp[0], B = wp[1], C = wp[2], Dq = wp[3];
        u64 E = *(const u64*)&w2_s[c*20 + 16];
        u64 w9[9] = {A.x,A.y,B.x,B.y,C.x,C.y,Dq.x,Dq.y,E};
        #pragma unroll
        for (int j = 0; j < 4; j++) {
            u64 v = pack2(tp[(size_t)c*HWW + j*256]);
            #pragma unroll
            for (int t = 0; t < 9; t++) acc[j][t] = ffma2(v, w9[t], acc[j][t]);
        }
    }

    float* op = g_off + (size_t)b*18*HWW + hw0 + tid;
    #pragma unroll
    for (int j = 0; j < 4; j++)
        #pragma unroll
        for (int t = 0; t < 9; t++) {
            op[(size_t)(2*t)*HWW + j*256]   = lo2(acc[j][t]) + __ldg(&b02[2*t]);
            op[(size_t)(2*t+1)*HWW + j*256] = hi2(acc[j][t]) + __ldg(&b02[2*t+1]);
        }
}

// ---------------------------------------------------------------------------
// Kernel 4: deformable conv via mma.sync bf16-split.
// ---------------------------------------------------------------------------
#define DEF_SMEM 69632

__global__ __launch_bounds__(256,1) void k_deform_mma(const float* __restrict__ db,
                                                      float* __restrict__ out)
{
    extern __shared__ char smem[];
    uint32_t sb = smem_u32(smem);
    int tid = threadIdx.x, lane = tid&31, wid = tid>>5;
    int pxb = blockIdx.x*128;
    int b = pxb/HWW, hw0 = pxb%HWW;
    float* pw_s = (float*)(smem + 65536);
    int*   pi_s = (int*)(smem + 65536 + 2048);

    auto issueW = [&](int t){
        int s = t&1;
        #pragma unroll
        for (int j = 0; j < 4; j++) {
            int c = tid + j*256;               // [0,1024)
            int split = c>>9, r = c&511;
            int co = r>>3, ci8 = r&7;
            const __nv_bfloat16* src = g_dwb + ((size_t)(split*9 + t)*4096 + co*64 + ci8*8);
            cp16(sb + 32768 + s*16384 + split*8192 + swz((uint32_t)(co*128 + ci8*16)), src);
        }
        CP_COMMIT();
    };
    issueW(0);

    int m0 = (wid>>1)*32, n0 = (wid&1)*32;
    float d[2][4][4];
    #pragma unroll
    for (int mt = 0; mt < 2; mt++)
        #pragma unroll
        for (int nt = 0; nt < 4; nt++)
            #pragma unroll
            for (int e = 0; e < 4; e++) d[mt][nt][e] = 0.f;

    const float* xb = g_xt + (size_t)b*HWW*64;

    #pragma unroll 1
    for (int k = 0; k < 9; k++) {
        if (tid < 128) {
            int px = tid, hw = hw0 + px;
            int h = hw/WW, w = hw - h*WW;
            int ky = k/3, kx = k - ky*3;
            const float* offb = g_off + (size_t)b*18*HWW + hw;
            float py  = (float)(h - 1 + ky) + offb[(size_t)(2*k)*HWW];
            float pxf = (float)(w - 1 + kx) + offb[(size_t)(2*k+1)*HWW];
            float fy = floorf(py), fx = floorf(pxf);
            int iy = (int)fy, ix = (int)fx;
            float wy = py - fy, wx = pxf - fx;
            bool vy0 = (iy   >= 0 && iy   < HH);
            bool vy1 = (iy+1 >= 0 && iy+1 < HH);
            bool vx0 = (ix   >= 0 && ix   < WW);
            bool vx1 = (ix+1 >= 0 && ix+1 < WW);
            float w00 = (1.f-wy)*(1.f-wx); if (!(vy0&&vx0)) w00 = 0.f;
            float w01 = (1.f-wy)*wx;       if (!(vy0&&vx1)) w01 = 0.f;
            float w10 = wy*(1.f-wx);       if (!(vy1&&vx0)) w10 = 0.f;
            float w11 = wy*wx;             if (!(vy1&&vx1)) w11 = 0.f;
            int cy0 = min(max(iy,0),HH-1),   cy1 = min(max(iy+1,0),HH-1);
            int cx0 = min(max(ix,0),WW-1),   cx1 = min(max(ix+1,0),WW-1);
            pw_s[px*4+0] = w00; pw_s[px*4+1] = w01;
            pw_s[px*4+2] = w10; pw_s[px*4+3] = w11;
            pi_s[px*4+0] = (cy0*WW + cx0)*64; pi_s[px*4+1] = (cy0*WW + cx1)*64;
            pi_s[px*4+2] = (cy1*WW + cx0)*64; pi_s[px*4+3] = (cy1*WW + cx1)*64;
        }
        if (k < 8) issueW(k+1);
        __syncthreads();

        {
            int px = tid>>1, ch0 = (tid&1)*32;
            float w00 = pw_s[px*4+0], w01v = pw_s[px*4+1];
            float w10 = pw_s[px*4+2], w11  = pw_s[px*4+3];
            int i00 = pi_s[px*4+0], i01 = pi_s[px*4+1];
            int i10 = pi_s[px*4+2], i11 = pi_s[px*4+3];
            #pragma unroll
            for (int q = 0; q < 8; q++) {
                int c = ch0 + q*4;
                float4 A = *(const float4*)(xb + i00 + c);
                float4 Bq= *(const float4*)(xb + i01 + c);
                float4 C = *(const float4*)(xb + i10 + c);
                float4 Dq= *(const float4*)(xb + i11 + c);
                float s0 = w00*A.x + w01v*Bq.x + w10*C.x + w11*Dq.x;
                float s1 = w00*A.y + w01v*Bq.y + w10*C.y + w11*Dq.y;
                float s2 = w00*A.z + w01v*Bq.z + w10*C.z + w11*Dq.z;
                float s3 = w00*A.w + w01v*Bq.w + w10*C.w + w11*Dq.w;
                __nv_bfloat16 h0 = __float2bfloat16(s0);
                __nv_bfloat16 h1 = __float2bfloat16(s1);
                __nv_bfloat16 h2 = __float2bfloat16(s2);
                __nv_bfloat16 h3 = __float2bfloat16(s3);
                uint32_t hp0 = (uint32_t)__bfloat16_as_ushort(h1)<<16 | __bfloat16_as_ushort(h0);
                uint32_t hp1 = (uint32_t)__bfloat16_as_ushort(h3)<<16 | __bfloat16_as_ushort(h2);
                __nv_bfloat162 lp0 = __floats2bfloat162_rn(s0 - __bfloat162float(h0),
                                                           s1 - __bfloat162float(h1));
                __nv_bfloat162 lp1 = __floats2bfloat162_rn(s2 - __bfloat162float(h2),
                                                           s3 - __bfloat162float(h3));
                uint32_t rel = (uint32_t)(px*128 + c*2);
                *(uint32_t*)(smem + swz(rel))          = hp0;
                *(uint32_t*)(smem + swz(rel+4))        = hp1;
                *(uint32_t*)(smem + 16384 + swz(rel))  = *(uint32_t*)&lp0;
                *(uint32_t*)(smem + 16384 + swz(rel+4))= *(uint32_t*)&lp1;
            }
        }
        if (k < 8) asm volatile("cp.async.wait_group 1;" ::: "memory");
        else       asm volatile("cp.async.wait_group 0;" ::: "memory");
        __syncthreads();

        uint32_t Ah = sb, Al = sb + 16384;
        uint32_t Bh = sb + 32768 + (uint32_t)((k&1)*16384);
        uint32_t Bl = Bh + 8192;
        #pragma unroll
        for (int ks = 0; ks < 4; ks++) {
            uint32_t ah[2][4], al[2][4], bh[4][2], bl[4][2];
            #pragma unroll
            for (int mt = 0; mt < 2; mt++) {
                uint32_t rel = (uint32_t)((m0 + mt*16 + (lane&15))*128
                                          + ks*32 + (lane>>4)*16);
                ldsm4(ah[mt], Ah + swz(rel));
                ldsm4(al[mt], Al + swz(rel));
            }
            #pragma unroll
            for (int nt2 = 0; nt2 < 2; nt2++) {
                int mid = lane>>3;
                int row = n0 + nt2*16 + (mid>>1)*8 + (lane&7);
                uint32_t rel = (uint32_t)(row*128 + ks*32 + (mid&1)*16);
                uint32_t r4[4];
                ldsm4(r4, Bh + swz(rel));
                bh[nt2*2][0]=r4[0]; bh[nt2*2][1]=r4[1];
                bh[nt2*2+1][0]=r4[2]; bh[nt2*2+1][1]=r4[3];
                ldsm4(r4, Bl + swz(rel));
                bl[nt2*2][0]=r4[0]; bl[nt2*2][1]=r4[1];
                bl[nt2*2+1][0]=r4[2]; bl[nt2*2+1][1]=r4[3];
            }
            #pragma unroll
            for (int mt = 0; mt < 2; mt++)
                #pragma unroll
                for (int nt = 0; nt < 4; nt++) {
                    mma_bf16(d[mt][nt], ah[mt], bh[nt]);
                    mma_bf16(d[mt][nt], ah[mt], bl[nt]);
                    mma_bf16(d[mt][nt], al[mt], bh[nt]);
                }
        }
        __syncthreads();
    }

    float* ep = (float*)smem;
    #pragma unroll
    for (int mt = 0; mt < 2; mt++)
        #pragma unroll
        for (int nt = 0; nt < 4; nt++) {
            int px = m0 + mt*16 + (lane>>2);
            int co = n0 + nt*8 + (lane&3)*2;
            ep[px*66 + co]       = d[mt][nt][0];
            ep[px*66 + co + 1]   = d[mt][nt][1];
            ep[(px+8)*66 + co]   = d[mt][nt][2];
            ep[(px+8)*66 + co+1] = d[mt][nt][3];
        }
    __syncthreads();
    float* op = out + (size_t)b*64*HWW + hw0;
    for (int i = tid; i < 8192; i += 256) {
        int co = i>>7, p = i&127;
        op[(size_t)co*HWW + p] = ep[p*66 + co] + __ldg(&db[co]);
    }
}

// ===========================================================================
extern "C" void kernel_launch(void* const* d_in, const int* in_sizes, int n_in,
                              void* d_out, int out_size)
{
    const float* in_aux = (const float*)d_in[0];
    const float* in_ref = (const float*)d_in[1];
    const float* w01    = (const float*)d_in[2];
    const float* b01    = (const float*)d_in[3];
    const float* a1w    = (const float*)d_in[4];
    const float* a1b    = (const float*)d_in[5];
    const float* a2w    = (const float*)d_in[6];
    const float* a2b    = (const float*)d_in[7];
    const float* a3w    = (const float*)d_in[8];
    const float* a3b    = (const float*)d_in[9];
    const float* arw    = (const float*)d_in[10];
    const float* arb    = (const float*)d_in[11];
    const float* w02    = (const float*)d_in[12];
    const float* b02    = (const float*)d_in[13];
    const float* dwp    = (const float*)d_in[14];
    const float* dbp    = (const float*)d_in[15];
    float* out = (float*)d_out;

    static int s_inited = 0;
    if (!s_inited) {
        cudaFuncSetAttribute(k_conv1_mma,  cudaFuncAttributeMaxDynamicSharedMemorySize, C1_SMEM);
        cudaFuncSetAttribute(k_aspp_mma,   cudaFuncAttributeMaxDynamicSharedMemorySize, ASPP_SMEM);
        cudaFuncSetAttribute(k_fuse_mma,   cudaFuncAttributeMaxDynamicSharedMemorySize, FUSE_SMEM);
        cudaFuncSetAttribute(k_deform_mma, cudaFuncAttributeMaxDynamicSharedMemorySize, DEF_SMEM);
        s_inited = 1;
    }

    k_prep<<<1317, 256>>>(w01, a1w, a2w, a3w, arw, w02, dwp);
    k_splitin<<<dim3(800, 4), 256>>>(in_aux, in_ref);
    k_conv1_mma<<<800, 256, C1_SMEM>>>(b01);

    dim3 ga(10, 20, 12);
    k_aspp_mma<<<ga, 256, ASPP_SMEM>>>(a1b, a2b, a3b);

    k_fuse_mma<<<800, 256, FUSE_SMEM>>>(arb);
    k_head<<<100, 256>>>(b02);
    k_deform_mma<<<800, 256, DEF_SMEM>>>(dbp, out);
}